// round 4
// baseline (speedup 1.0000x reference)
#include <cuda_runtime.h>
#include <cuda_bf16.h>
#include <cstdint>

// Problem constants (reference: N=100000, E=1600000, IN=HID=128, OUT=64)
#define NMAX 100000
#define FIN  128
#define FHID 128
#define FOUT 64
#define SCAN_BLK 1024

// ---------------------------------------------------------------------------
// Device-global scratch (no allocation allowed)
// ---------------------------------------------------------------------------
__device__ int   g_deg[NMAX];                 // target degree (without self-loop)
__device__ int   g_off[NMAX + 1];             // CSR offsets (exclusive scan of deg)
__device__ int   g_cursor[NMAX];              // placement cursors
__device__ int   g_bsum[128];                 // block sums for scan
__device__ float g_dinv[NMAX];                // rsqrt(deg+1)
__device__ int   g_eidx[1600000];             // CSR: source row per edge, grouped by col
__device__ float g_Hs [(size_t)NMAX * FHID];  // (X@W1) * dinv[row]
__device__ float g_H2 [(size_t)NMAX * FHID];  // relu(dinv*agg1 + b1)
__device__ float g_Hs2[(size_t)NMAX * FOUT];  // (H2@W2) * dinv[row]

// ---------------------------------------------------------------------------
// CSR build: degree count -> 3-pass scan -> placement; also dinv.
// ---------------------------------------------------------------------------
__global__ void k_zero_deg(int N) {
    int i = blockIdx.x * blockDim.x + threadIdx.x;
    if (i < N) g_deg[i] = 0;
}

__global__ void k_count(const int* __restrict__ col, int E) {
    int e = blockIdx.x * blockDim.x + threadIdx.x;
    if (e < E) atomicAdd(&g_deg[col[e]], 1);
}

// Pass 1: per-block inclusive scan of deg; writes exclusive partials + block sums.
__global__ __launch_bounds__(SCAN_BLK) void k_scan_block(int N) {
    __shared__ int s[SCAN_BLK];
    int t = threadIdx.x;
    int i = blockIdx.x * SCAN_BLK + t;
    int v = (i < N) ? g_deg[i] : 0;
    s[t] = v;
    __syncthreads();
#pragma unroll
    for (int d = 1; d < SCAN_BLK; d <<= 1) {
        int x = s[t];
        if (t >= d) x += s[t - d];
        __syncthreads();
        s[t] = x;
        __syncthreads();
    }
    if (i < N) g_off[i] = s[t] - v;              // exclusive partial
    if (t == SCAN_BLK - 1) g_bsum[blockIdx.x] = s[t];
}

// Pass 2: single block scans the (<=128) block sums, in place, exclusive.
__global__ __launch_bounds__(128) void k_scan_tops(int nb) {
    __shared__ int s[128];
    int t = threadIdx.x;
    int v = (t < nb) ? g_bsum[t] : 0;
    s[t] = v;
    __syncthreads();
#pragma unroll
    for (int d = 1; d < 128; d <<= 1) {
        int x = s[t];
        if (t >= d) x += s[t - d];
        __syncthreads();
        s[t] = x;
        __syncthreads();
    }
    if (t < nb) g_bsum[t] = s[t] - v;            // exclusive
}

// Pass 3: add block offsets; init cursors; compute dinv; close off[N].
__global__ void k_scan_add(int N, int E) {
    int i = blockIdx.x * blockDim.x + threadIdx.x;
    if (i < N) {
        int o = g_off[i] + g_bsum[i / SCAN_BLK];
        g_off[i]    = o;
        g_cursor[i] = o;
        g_dinv[i]   = rsqrtf((float)g_deg[i] + 1.0f);
    }
    if (i == 0) g_off[N] = E;
}

__global__ void k_place(const int* __restrict__ row, const int* __restrict__ col, int E) {
    int e = blockIdx.x * blockDim.x + threadIdx.x;
    if (e < E) {
        int c = col[e];
        int p = atomicAdd(&g_cursor[c], 1);
        g_eidx[p] = row[e];
    }
}

// ---------------------------------------------------------------------------
// GEMM1: Hs = (X @ W1) * dinv[row]
// BM=128, BN=128, BK=16, 256 threads, 8x8 microtile.
// Double-buffered smem; register-staged prefetch; 1 barrier / 16 k-steps.
// ---------------------------------------------------------------------------
__global__ __launch_bounds__(256) void k_gemm1(
    const float* __restrict__ X, const float* __restrict__ W, int N)
{
    __shared__ float As[2][16][128];
    __shared__ float Bs[2][16][128];

    const int bi  = blockIdx.x * 128;
    const int tid = threadIdx.x;
    const int tx  = tid & 15;          // 16 col-groups of 8
    const int ty  = tid >> 4;          // 16 row-groups of 8

    // X loader: 128 rows x 16 k = 512 float4, 2 per thread
    const int xr  = tid >> 1;          // 0..127
    const int xk  = (tid & 1) * 8;     // 0 or 8
    // W loader: 16 k-rows x 128 cols = 512 float4, 2 per thread
    const int wr  = tid >> 4;          // 0..15
    const int wc  = (tid & 15) * 8;    // 0..120

    const int gr = bi + xr;
    const bool xok = (gr < N);
    const float* Xrow = X + (size_t)gr * FIN;

    float4 xa, xb, wa, wb;

    // Prologue: tile 0
    xa = xok ? *(const float4*)&Xrow[xk]     : make_float4(0.f,0.f,0.f,0.f);
    xb = xok ? *(const float4*)&Xrow[xk + 4] : make_float4(0.f,0.f,0.f,0.f);
    wa = *(const float4*)&W[(size_t)wr * FHID + wc];
    wb = *(const float4*)&W[(size_t)wr * FHID + wc + 4];
    As[0][xk + 0][xr] = xa.x; As[0][xk + 1][xr] = xa.y;
    As[0][xk + 2][xr] = xa.z; As[0][xk + 3][xr] = xa.w;
    As[0][xk + 4][xr] = xb.x; As[0][xk + 5][xr] = xb.y;
    As[0][xk + 6][xr] = xb.z; As[0][xk + 7][xr] = xb.w;
    *(float4*)&Bs[0][wr][wc]     = wa;
    *(float4*)&Bs[0][wr][wc + 4] = wb;
    __syncthreads();

    float acc[8][8];
#pragma unroll
    for (int i = 0; i < 8; i++)
#pragma unroll
        for (int j = 0; j < 8; j++) acc[i][j] = 0.f;

#pragma unroll
    for (int t = 0; t < FIN / 16; t++) {
        const int cur  = t & 1;
        const bool more = (t < FIN / 16 - 1);
        if (more) {
            const int k0 = (t + 1) * 16;
            xa = xok ? *(const float4*)&Xrow[k0 + xk]     : make_float4(0.f,0.f,0.f,0.f);
            xb = xok ? *(const float4*)&Xrow[k0 + xk + 4] : make_float4(0.f,0.f,0.f,0.f);
            wa = *(const float4*)&W[(size_t)(k0 + wr) * FHID + wc];
            wb = *(const float4*)&W[(size_t)(k0 + wr) * FHID + wc + 4];
        }
#pragma unroll
        for (int k = 0; k < 16; k++) {
            float a[8], b[8];
            *(float4*)&a[0] = *(const float4*)&As[cur][k][ty * 8];
            *(float4*)&a[4] = *(const float4*)&As[cur][k][ty * 8 + 4];
            *(float4*)&b[0] = *(const float4*)&Bs[cur][k][tx * 8];
            *(float4*)&b[4] = *(const float4*)&Bs[cur][k][tx * 8 + 4];
#pragma unroll
            for (int i = 0; i < 8; i++)
#pragma unroll
                for (int j = 0; j < 8; j++)
                    acc[i][j] = fmaf(a[i], b[j], acc[i][j]);
        }
        if (more) {
            const int nb = cur ^ 1;
            As[nb][xk + 0][xr] = xa.x; As[nb][xk + 1][xr] = xa.y;
            As[nb][xk + 2][xr] = xa.z; As[nb][xk + 3][xr] = xa.w;
            As[nb][xk + 4][xr] = xb.x; As[nb][xk + 5][xr] = xb.y;
            As[nb][xk + 6][xr] = xb.z; As[nb][xk + 7][xr] = xb.w;
            *(float4*)&Bs[nb][wr][wc]     = wa;
            *(float4*)&Bs[nb][wr][wc + 4] = wb;
            __syncthreads();
        }
    }

#pragma unroll
    for (int i = 0; i < 8; i++) {
        int r = bi + ty * 8 + i;
        if (r < N) {
            float s = g_dinv[r];
#pragma unroll
            for (int j = 0; j < 8; j += 4) {
                float4 v;
                v.x = acc[i][j + 0] * s;
                v.y = acc[i][j + 1] * s;
                v.z = acc[i][j + 2] * s;
                v.w = acc[i][j + 3] * s;
                *(float4*)&g_Hs[(size_t)r * FHID + tx * 8 + j] = v;
            }
        }
    }
}

// ---------------------------------------------------------------------------
// Agg1 (CSR gather): one warp per node, lane = float4 of 128 feats.
// acc = Hs[v] (self-loop) + sum_{edges->v} Hs[src]; H2 = relu(dinv[v]*acc + b1).
// ---------------------------------------------------------------------------
__global__ __launch_bounds__(256) void k_agg1(const float* __restrict__ b1, int N) {
    int w    = (blockIdx.x * blockDim.x + threadIdx.x) >> 5;
    int lane = threadIdx.x & 31;
    if (w >= N) return;
    const float4* Hs4 = (const float4*)g_Hs;
    int beg = g_off[w], end = g_off[w + 1];

    float4 acc = Hs4[(size_t)w * 32 + lane];      // self-loop term
    for (int j0 = beg; j0 < end; j0 += 32) {
        int jj = j0 + lane;
        int myidx = (jj < end) ? g_eidx[jj] : 0;
        int m = min(32, end - j0);
        for (int t = 0; t < m; t++) {
            int r = __shfl_sync(0xffffffffu, myidx, t);
            float4 v = Hs4[(size_t)r * 32 + lane];
            acc.x += v.x; acc.y += v.y; acc.z += v.z; acc.w += v.w;
        }
    }
    float s = g_dinv[w];
    float4 bb = ((const float4*)b1)[lane];
    float4 o;
    o.x = fmaxf(fmaf(acc.x, s, bb.x), 0.f);
    o.y = fmaxf(fmaf(acc.y, s, bb.y), 0.f);
    o.z = fmaxf(fmaf(acc.z, s, bb.z), 0.f);
    o.w = fmaxf(fmaf(acc.w, s, bb.w), 0.f);
    ((float4*)g_H2)[(size_t)w * 32 + lane] = o;
}

// ---------------------------------------------------------------------------
// GEMM2: Hs2 = (H2 @ W2) * dinv[row]
// BM=128, BN=64, BK=16, 256 threads, 8x4 microtile, double-buffered.
// ---------------------------------------------------------------------------
__global__ __launch_bounds__(256) void k_gemm2(
    const float* __restrict__ W2, int N)
{
    __shared__ float As[2][16][128];
    __shared__ float Bs[2][16][64];

    const int bi  = blockIdx.x * 128;
    const int tid = threadIdx.x;
    const int tx  = tid & 15;          // 16 col-groups of 4 -> 64
    const int ty  = tid >> 4;          // 16 row-groups of 8 -> 128

    const int xr  = tid >> 1;          // 0..127
    const int xk  = (tid & 1) * 8;     // 0 or 8
    // W2 loader: 16 k-rows x 64 cols = 256 float4, 1 per thread
    const int wr  = tid >> 4;          // 0..15
    const int wc  = (tid & 15) * 4;    // 0..60

    const int gr = bi + xr;
    const bool xok = (gr < N);
    const float* Hrow = g_H2 + (size_t)gr * FHID;

    float4 xa, xb, wa;

    xa = xok ? *(const float4*)&Hrow[xk]     : make_float4(0.f,0.f,0.f,0.f);
    xb = xok ? *(const float4*)&Hrow[xk + 4] : make_float4(0.f,0.f,0.f,0.f);
    wa = *(const float4*)&W2[(size_t)wr * FOUT + wc];
    As[0][xk + 0][xr] = xa.x; As[0][xk + 1][xr] = xa.y;
    As[0][xk + 2][xr] = xa.z; As[0][xk + 3][xr] = xa.w;
    As[0][xk + 4][xr] = xb.x; As[0][xk + 5][xr] = xb.y;
    As[0][xk + 6][xr] = xb.z; As[0][xk + 7][xr] = xb.w;
    *(float4*)&Bs[0][wr][wc] = wa;
    __syncthreads();

    float acc[8][4];
#pragma unroll
    for (int i = 0; i < 8; i++)
#pragma unroll
        for (int j = 0; j < 4; j++) acc[i][j] = 0.f;

#pragma unroll
    for (int t = 0; t < FHID / 16; t++) {
        const int cur  = t & 1;
        const bool more = (t < FHID / 16 - 1);
        if (more) {
            const int k0 = (t + 1) * 16;
            xa = xok ? *(const float4*)&Hrow[k0 + xk]     : make_float4(0.f,0.f,0.f,0.f);
            xb = xok ? *(const float4*)&Hrow[k0 + xk + 4] : make_float4(0.f,0.f,0.f,0.f);
            wa = *(const float4*)&W2[(size_t)(k0 + wr) * FOUT + wc];
        }
#pragma unroll
        for (int k = 0; k < 16; k++) {
            float a[8], b[4];
            *(float4*)&a[0] = *(const float4*)&As[cur][k][ty * 8];
            *(float4*)&a[4] = *(const float4*)&As[cur][k][ty * 8 + 4];
            *(float4*)&b[0] = *(const float4*)&Bs[cur][k][tx * 4];
#pragma unroll
            for (int i = 0; i < 8; i++)
#pragma unroll
                for (int j = 0; j < 4; j++)
                    acc[i][j] = fmaf(a[i], b[j], acc[i][j]);
        }
        if (more) {
            const int nb = cur ^ 1;
            As[nb][xk + 0][xr] = xa.x; As[nb][xk + 1][xr] = xa.y;
            As[nb][xk + 2][xr] = xa.z; As[nb][xk + 3][xr] = xa.w;
            As[nb][xk + 4][xr] = xb.x; As[nb][xk + 5][xr] = xb.y;
            As[nb][xk + 6][xr] = xb.z; As[nb][xk + 7][xr] = xb.w;
            *(float4*)&Bs[nb][wr][wc] = wa;
            __syncthreads();
        }
    }

#pragma unroll
    for (int i = 0; i < 8; i++) {
        int r = bi + ty * 8 + i;
        if (r < N) {
            float s = g_dinv[r];
            float4 v;
            v.x = acc[i][0] * s;
            v.y = acc[i][1] * s;
            v.z = acc[i][2] * s;
            v.w = acc[i][3] * s;
            *(float4*)&g_Hs2[(size_t)r * FOUT + tx * 4] = v;
        }
    }
}

// ---------------------------------------------------------------------------
// Agg2 (CSR gather): one warp per node, lane = float2 of 64 feats.
// out = dinv[v]*(Hs2[v] + sum Hs2[src]) + b2  -> writes d_out directly.
// ---------------------------------------------------------------------------
__global__ __launch_bounds__(256) void k_agg2(
    const float* __restrict__ b2, float* __restrict__ out, int N)
{
    int w    = (blockIdx.x * blockDim.x + threadIdx.x) >> 5;
    int lane = threadIdx.x & 31;
    if (w >= N) return;
    const float2* Hs2v = (const float2*)g_Hs2;
    int beg = g_off[w], end = g_off[w + 1];

    float2 acc = Hs2v[(size_t)w * 32 + lane];     // self-loop term
    for (int j0 = beg; j0 < end; j0 += 32) {
        int jj = j0 + lane;
        int myidx = (jj < end) ? g_eidx[jj] : 0;
        int m = min(32, end - j0);
        for (int t = 0; t < m; t++) {
            int r = __shfl_sync(0xffffffffu, myidx, t);
            float2 v = Hs2v[(size_t)r * 32 + lane];
            acc.x += v.x; acc.y += v.y;
        }
    }
    float s = g_dinv[w];
    float2 bb = ((const float2*)b2)[lane];
    float2 o;
    o.x = fmaf(acc.x, s, bb.x);
    o.y = fmaf(acc.y, s, bb.y);
    ((float2*)out)[(size_t)w * 32 + lane] = o;
}

// ---------------------------------------------------------------------------
// Launch
// ---------------------------------------------------------------------------
extern "C" void kernel_launch(void* const* d_in, const int* in_sizes, int n_in,
                              void* d_out, int out_size)
{
    const float* x  = (const float*)d_in[0];
    const int*   ei = (const int*)  d_in[1];
    const float* W1 = (const float*)d_in[2];
    const float* b1 = (const float*)d_in[3];
    const float* W2 = (const float*)d_in[4];
    const float* b2 = (const float*)d_in[5];
    float* out = (float*)d_out;

    const int N = in_sizes[0] / FIN;     // 100000
    const int E = in_sizes[1] / 2;       // 1600000
    const int* row = ei;       // sources
    const int* col = ei + E;   // targets

    const int nb = (N + SCAN_BLK - 1) / SCAN_BLK;   // 98

    // CSR build + dinv
    k_zero_deg  <<<(N + 255) / 256, 256>>>(N);
    k_count     <<<(E + 255) / 256, 256>>>(col, E);
    k_scan_block<<<nb, SCAN_BLK>>>(N);
    k_scan_tops <<<1, 128>>>(nb);
    k_scan_add  <<<(N + 255) / 256, 256>>>(N, E);
    k_place     <<<(E + 255) / 256, 256>>>(row, col, E);

    // Layer 1
    k_gemm1<<<(N + 127) / 128, 256>>>(x, W1, N);
    k_agg1 <<<(N * 32 + 255) / 256, 256>>>(b1, N);

    // Layer 2
    k_gemm2<<<(N + 127) / 128, 256>>>(W2, N);
    k_agg2 <<<(N * 32 + 255) / 256, 256>>>(b2, out, N);
}

// round 5
// speedup vs baseline: 1.3315x; 1.3315x over previous
#include <cuda_runtime.h>
#include <cuda_bf16.h>
#include <cstdint>

// Problem constants (reference: N=100000, E=1600000, IN=HID=128, OUT=64)
#define NMAX 100000
#define FIN  128
#define FHID 128
#define FOUT 64
#define SCAN_BLK 1024

#define CP_ASYNC16(dst_u32, src_ptr) \
    asm volatile("cp.async.cg.shared.global [%0], [%1], 16;" :: "r"(dst_u32), "l"(src_ptr))
#define CP_COMMIT()  asm volatile("cp.async.commit_group;")
#define CP_WAIT0()   asm volatile("cp.async.wait_group 0;")

// ---------------------------------------------------------------------------
// Device-global scratch (no allocation allowed)
// ---------------------------------------------------------------------------
__device__ int   g_deg[NMAX];                 // target degree (without self-loop)
__device__ int   g_off[NMAX + 1];             // CSR offsets (exclusive scan of deg)
__device__ int   g_cursor[NMAX];              // placement cursors
__device__ int   g_bsum[128];                 // block sums for scan
__device__ float g_dinv[NMAX];                // rsqrt(deg+1)
__device__ int   g_eidx[1600000];             // CSR: source row per edge, grouped by col
__device__ float g_Hs [(size_t)NMAX * FHID];  // (X@W1) * dinv[row]
__device__ float g_H2 [(size_t)NMAX * FHID];  // relu(dinv*agg1 + b1)
__device__ float g_Hs2[(size_t)NMAX * FOUT];  // (H2@W2) * dinv[row]

// ---------------------------------------------------------------------------
// CSR build: degree count -> 3-pass scan -> placement; also dinv.
// ---------------------------------------------------------------------------
__global__ void k_zero_deg(int N) {
    int i = blockIdx.x * blockDim.x + threadIdx.x;
    if (i < N) g_deg[i] = 0;
}

__global__ void k_count(const int* __restrict__ col, int E) {
    int e = blockIdx.x * blockDim.x + threadIdx.x;
    if (e < E) atomicAdd(&g_deg[col[e]], 1);
}

// Pass 1: per-block inclusive scan of deg; writes exclusive partials + block sums.
__global__ __launch_bounds__(SCAN_BLK) void k_scan_block(int N) {
    __shared__ int s[SCAN_BLK];
    int t = threadIdx.x;
    int i = blockIdx.x * SCAN_BLK + t;
    int v = (i < N) ? g_deg[i] : 0;
    s[t] = v;
    __syncthreads();
#pragma unroll
    for (int d = 1; d < SCAN_BLK; d <<= 1) {
        int x = s[t];
        if (t >= d) x += s[t - d];
        __syncthreads();
        s[t] = x;
        __syncthreads();
    }
    if (i < N) g_off[i] = s[t] - v;              // exclusive partial
    if (t == SCAN_BLK - 1) g_bsum[blockIdx.x] = s[t];
}

// Pass 2: single block scans the (<=128) block sums, in place, exclusive.
__global__ __launch_bounds__(128) void k_scan_tops(int nb) {
    __shared__ int s[128];
    int t = threadIdx.x;
    int v = (t < nb) ? g_bsum[t] : 0;
    s[t] = v;
    __syncthreads();
#pragma unroll
    for (int d = 1; d < 128; d <<= 1) {
        int x = s[t];
        if (t >= d) x += s[t - d];
        __syncthreads();
        s[t] = x;
        __syncthreads();
    }
    if (t < nb) g_bsum[t] = s[t] - v;            // exclusive
}

// Pass 3: add block offsets; init cursors; compute dinv; close off[N].
__global__ void k_scan_add(int N, int E) {
    int i = blockIdx.x * blockDim.x + threadIdx.x;
    if (i < N) {
        int o = g_off[i] + g_bsum[i / SCAN_BLK];
        g_off[i]    = o;
        g_cursor[i] = o;
        g_dinv[i]   = rsqrtf((float)g_deg[i] + 1.0f);
    }
    if (i == 0) g_off[N] = E;
}

__global__ void k_place(const int* __restrict__ row, const int* __restrict__ col, int E) {
    int e = blockIdx.x * blockDim.x + threadIdx.x;
    if (e < E) {
        int c = col[e];
        int p = atomicAdd(&g_cursor[c], 1);
        g_eidx[p] = row[e];
    }
}

// ---------------------------------------------------------------------------
// GEMM1: Hs = (X @ W1) * dinv[row]
// BM=128, BN=128, BK=8, 256 threads, 8x8 microtile.
// 2-stage double buffer: B tile via cp.async.cg; A tile via 1-float4 register
// prefetch + transpose-on-store. One barrier per tile.
// ---------------------------------------------------------------------------
__global__ __launch_bounds__(256) void k_gemm1(
    const float* __restrict__ X, const float* __restrict__ W, int N)
{
    __shared__ float As[2][8][128];
    __shared__ float Bs[2][8][128];

    const int bi  = blockIdx.x * 128;
    const int tid = threadIdx.x;
    const int tx  = tid & 15;          // 16 col-groups of 8
    const int ty  = tid >> 4;          // 16 row-groups of 8

    // X loader: 128 rows x 8 k = 256 float4, 1 per thread
    const int xr  = tid >> 1;          // 0..127
    const int xc4 = (tid & 1) * 4;     // 0 or 4
    // W loader: 8 k-rows x 128 cols = 256 float4, 1 per thread
    const int wr  = tid >> 5;          // 0..7
    const int wc4 = (tid & 31) * 4;    // 0..124

    const int grc = min(bi + xr, N - 1);            // clamped (garbage rows discarded)
    const float* Xrow = X + (size_t)grc * FIN + xc4;

    // cp.async destination for this thread's B chunk (per stage)
    uint32_t bdst0 = (uint32_t)__cvta_generic_to_shared(&Bs[0][wr][wc4]);
    uint32_t bdst1 = (uint32_t)__cvta_generic_to_shared(&Bs[1][wr][wc4]);
    const float* wsrc = W + (size_t)wr * FHID + wc4;

    // Prologue: stage 0
    float4 xa = *(const float4*)Xrow;
    CP_ASYNC16(bdst0, wsrc);
    CP_COMMIT();
    As[0][xc4 + 0][xr] = xa.x;
    As[0][xc4 + 1][xr] = xa.y;
    As[0][xc4 + 2][xr] = xa.z;
    As[0][xc4 + 3][xr] = xa.w;
    CP_WAIT0();
    __syncthreads();

    float acc[8][8];
#pragma unroll
    for (int i = 0; i < 8; i++)
#pragma unroll
        for (int j = 0; j < 8; j++) acc[i][j] = 0.f;

    for (int t = 0; t < FIN / 8; t++) {
        const int cur = t & 1;
        const bool more = (t < FIN / 8 - 1);
        if (more) {
            const int k0 = (t + 1) * 8;
            xa = *(const float4*)&Xrow[k0];
            CP_ASYNC16(cur ? bdst0 : bdst1, wsrc + (size_t)k0 * FHID);
            CP_COMMIT();
        }
#pragma unroll
        for (int k = 0; k < 8; k++) {
            float a[8], b[8];
            *(float4*)&a[0] = *(const float4*)&As[cur][k][ty * 8];
            *(float4*)&a[4] = *(const float4*)&As[cur][k][ty * 8 + 4];
            *(float4*)&b[0] = *(const float4*)&Bs[cur][k][tx * 8];
            *(float4*)&b[4] = *(const float4*)&Bs[cur][k][tx * 8 + 4];
#pragma unroll
            for (int i = 0; i < 8; i++)
#pragma unroll
                for (int j = 0; j < 8; j++)
                    acc[i][j] = fmaf(a[i], b[j], acc[i][j]);
        }
        if (more) {
            const int nb = cur ^ 1;
            As[nb][xc4 + 0][xr] = xa.x;
            As[nb][xc4 + 1][xr] = xa.y;
            As[nb][xc4 + 2][xr] = xa.z;
            As[nb][xc4 + 3][xr] = xa.w;
            CP_WAIT0();
            __syncthreads();
        }
    }

#pragma unroll
    for (int i = 0; i < 8; i++) {
        int r = bi + ty * 8 + i;
        if (r < N) {
            float s = g_dinv[r];
#pragma unroll
            for (int j = 0; j < 8; j += 4) {
                float4 v;
                v.x = acc[i][j + 0] * s;
                v.y = acc[i][j + 1] * s;
                v.z = acc[i][j + 2] * s;
                v.w = acc[i][j + 3] * s;
                *(float4*)&g_Hs[(size_t)r * FHID + tx * 8 + j] = v;
            }
        }
    }
}

// ---------------------------------------------------------------------------
// Agg1 (CSR gather): one warp per node, lane = float4 of 128 feats.
// acc = Hs[v] (self-loop) + sum_{edges->v} Hs[src]; H2 = relu(dinv[v]*acc + b1).
// ---------------------------------------------------------------------------
__global__ __launch_bounds__(256) void k_agg1(const float* __restrict__ b1, int N) {
    int w    = (blockIdx.x * blockDim.x + threadIdx.x) >> 5;
    int lane = threadIdx.x & 31;
    if (w >= N) return;
    const float4* Hs4 = (const float4*)g_Hs;
    int beg = g_off[w], end = g_off[w + 1];

    float4 acc = Hs4[(size_t)w * 32 + lane];      // self-loop term
    for (int j0 = beg; j0 < end; j0 += 32) {
        int jj = j0 + lane;
        int myidx = (jj < end) ? g_eidx[jj] : 0;
        int m = min(32, end - j0);
        for (int t = 0; t < m; t++) {
            int r = __shfl_sync(0xffffffffu, myidx, t);
            float4 v = Hs4[(size_t)r * 32 + lane];
            acc.x += v.x; acc.y += v.y; acc.z += v.z; acc.w += v.w;
        }
    }
    float s = g_dinv[w];
    float4 bb = ((const float4*)b1)[lane];
    float4 o;
    o.x = fmaxf(fmaf(acc.x, s, bb.x), 0.f);
    o.y = fmaxf(fmaf(acc.y, s, bb.y), 0.f);
    o.z = fmaxf(fmaf(acc.z, s, bb.z), 0.f);
    o.w = fmaxf(fmaf(acc.w, s, bb.w), 0.f);
    ((float4*)g_H2)[(size_t)w * 32 + lane] = o;
}

// ---------------------------------------------------------------------------
// GEMM2: Hs2 = (H2 @ W2) * dinv[row]
// BM=128, BN=64, BK=8, 256 threads, 8x4 microtile, cp.async 2-stage.
// ---------------------------------------------------------------------------
__global__ __launch_bounds__(256) void k_gemm2(
    const float* __restrict__ W2, int N)
{
    __shared__ float As[2][8][128];
    __shared__ float Bs[2][8][64];

    const int bi  = blockIdx.x * 128;
    const int tid = threadIdx.x;
    const int tx  = tid & 15;          // 16 col-groups of 4 -> 64
    const int ty  = tid >> 4;          // 16 row-groups of 8 -> 128

    const int xr  = tid >> 1;          // 0..127
    const int xc4 = (tid & 1) * 4;     // 0 or 4
    // W2 loader: 8 k-rows x 64 cols = 128 float4; first 128 threads only
    const int wr  = tid >> 4;          // 0..15 (only 0..7 used)
    const int wc4 = (tid & 15) * 4;    // 0..60
    const bool wok = (tid < 128);

    const int grc = min(bi + xr, N - 1);
    const float* Hrow = g_H2 + (size_t)grc * FHID + xc4;

    uint32_t bdst0 = (uint32_t)__cvta_generic_to_shared(&Bs[0][wr & 7][wc4]);
    uint32_t bdst1 = (uint32_t)__cvta_generic_to_shared(&Bs[1][wr & 7][wc4]);
    const float* wsrc = W2 + (size_t)(wr & 7) * FOUT + wc4;

    float4 xa = *(const float4*)Hrow;
    if (wok) CP_ASYNC16(bdst0, wsrc);
    CP_COMMIT();
    As[0][xc4 + 0][xr] = xa.x;
    As[0][xc4 + 1][xr] = xa.y;
    As[0][xc4 + 2][xr] = xa.z;
    As[0][xc4 + 3][xr] = xa.w;
    CP_WAIT0();
    __syncthreads();

    float acc[8][4];
#pragma unroll
    for (int i = 0; i < 8; i++)
#pragma unroll
        for (int j = 0; j < 4; j++) acc[i][j] = 0.f;

    for (int t = 0; t < FHID / 8; t++) {
        const int cur = t & 1;
        const bool more = (t < FHID / 8 - 1);
        if (more) {
            const int k0 = (t + 1) * 8;
            xa = *(const float4*)&Hrow[k0];
            if (wok) CP_ASYNC16(cur ? bdst0 : bdst1, wsrc + (size_t)k0 * FOUT);
            CP_COMMIT();
        }
#pragma unroll
        for (int k = 0; k < 8; k++) {
            float a[8], b[4];
            *(float4*)&a[0] = *(const float4*)&As[cur][k][ty * 8];
            *(float4*)&a[4] = *(const float4*)&As[cur][k][ty * 8 + 4];
            *(float4*)&b[0] = *(const float4*)&Bs[cur][k][tx * 4];
#pragma unroll
            for (int i = 0; i < 8; i++)
#pragma unroll
                for (int j = 0; j < 4; j++)
                    acc[i][j] = fmaf(a[i], b[j], acc[i][j]);
        }
        if (more) {
            const int nb = cur ^ 1;
            As[nb][xc4 + 0][xr] = xa.x;
            As[nb][xc4 + 1][xr] = xa.y;
            As[nb][xc4 + 2][xr] = xa.z;
            As[nb][xc4 + 3][xr] = xa.w;
            CP_WAIT0();
            __syncthreads();
        }
    }

#pragma unroll
    for (int i = 0; i < 8; i++) {
        int r = bi + ty * 8 + i;
        if (r < N) {
            float s = g_dinv[r];
            float4 v;
            v.x = acc[i][0] * s;
            v.y = acc[i][1] * s;
            v.z = acc[i][2] * s;
            v.w = acc[i][3] * s;
            *(float4*)&g_Hs2[(size_t)r * FOUT + tx * 4] = v;
        }
    }
}

// ---------------------------------------------------------------------------
// Agg2 (CSR gather): one warp per node, lane = float2 of 64 feats.
// out = dinv[v]*(Hs2[v] + sum Hs2[src]) + b2  -> writes d_out directly.
// ---------------------------------------------------------------------------
__global__ __launch_bounds__(256) void k_agg2(
    const float* __restrict__ b2, float* __restrict__ out, int N)
{
    int w    = (blockIdx.x * blockDim.x + threadIdx.x) >> 5;
    int lane = threadIdx.x & 31;
    if (w >= N) return;
    const float2* Hs2v = (const float2*)g_Hs2;
    int beg = g_off[w], end = g_off[w + 1];

    float2 acc = Hs2v[(size_t)w * 32 + lane];     // self-loop term
    for (int j0 = beg; j0 < end; j0 += 32) {
        int jj = j0 + lane;
        int myidx = (jj < end) ? g_eidx[jj] : 0;
        int m = min(32, end - j0);
        for (int t = 0; t < m; t++) {
            int r = __shfl_sync(0xffffffffu, myidx, t);
            float2 v = Hs2v[(size_t)r * 32 + lane];
            acc.x += v.x; acc.y += v.y;
        }
    }
    float s = g_dinv[w];
    float2 bb = ((const float2*)b2)[lane];
    float2 o;
    o.x = fmaf(acc.x, s, bb.x);
    o.y = fmaf(acc.y, s, bb.y);
    ((float2*)out)[(size_t)w * 32 + lane] = o;
}

// ---------------------------------------------------------------------------
// Launch
// ---------------------------------------------------------------------------
extern "C" void kernel_launch(void* const* d_in, const int* in_sizes, int n_in,
                              void* d_out, int out_size)
{
    const float* x  = (const float*)d_in[0];
    const int*   ei = (const int*)  d_in[1];
    const float* W1 = (const float*)d_in[2];
    const float* b1 = (const float*)d_in[3];
    const float* W2 = (const float*)d_in[4];
    const float* b2 = (const float*)d_in[5];
    float* out = (float*)d_out;

    const int N = in_sizes[0] / FIN;     // 100000
    const int E = in_sizes[1] / 2;       // 1600000
    const int* row = ei;       // sources
    const int* col = ei + E;   // targets

    const int nb = (N + SCAN_BLK - 1) / SCAN_BLK;   // 98

    // CSR build + dinv
    k_zero_deg  <<<(N + 255) / 256, 256>>>(N);
    k_count     <<<(E + 255) / 256, 256>>>(col, E);
    k_scan_block<<<nb, SCAN_BLK>>>(N);
    k_scan_tops <<<1, 128>>>(nb);
    k_scan_add  <<<(N + 255) / 256, 256>>>(N, E);
    k_place     <<<(E + 255) / 256, 256>>>(row, col, E);

    // Layer 1
    k_gemm1<<<(N + 127) / 128, 256>>>(x, W1, N);
    k_agg1 <<<(N * 32 + 255) / 256, 256>>>(b1, N);

    // Layer 2
    k_gemm2<<<(N + 127) / 128, 256>>>(W2, N);
    k_agg2 <<<(N * 32 + 255) / 256, 256>>>(b2, out, N);
}

// round 8
// speedup vs baseline: 1.6662x; 1.2514x over previous
#include <cuda_runtime.h>
#include <cuda_bf16.h>
#include <cstdint>

// Problem constants (reference: N=100000, E=1600000, IN=HID=128, OUT=64)
#define NMAX 100000
#define FIN  128
#define FHID 128
#define FOUT 64
#define SCAN_BLK 1024

// ---------------------------------------------------------------------------
// Device-global scratch (no allocation allowed)
// ---------------------------------------------------------------------------
__device__ int   g_deg[NMAX];
__device__ int   g_off[NMAX + 1];
__device__ int   g_cursor[NMAX];
__device__ int   g_bsum[128];
__device__ float g_dinv[NMAX];
__device__ int   g_eidx[1600000];
__device__ float g_Hs [(size_t)NMAX * FHID];  // (X@W1) * dinv[row]
__device__ float g_H2 [(size_t)NMAX * FHID];  // relu(dinv*agg1 + b1)
__device__ float g_Hs2[(size_t)NMAX * FOUT];  // (H2@W2) * dinv[row]

// ---------------------------------------------------------------------------
// Helpers
// ---------------------------------------------------------------------------
__device__ __forceinline__ void split_pack(float f0, float f1, uint32_t& hi, uint32_t& lo) {
    __nv_bfloat16 h0 = __float2bfloat16_rn(f0);
    __nv_bfloat16 h1 = __float2bfloat16_rn(f1);
    __nv_bfloat16 l0 = __float2bfloat16_rn(f0 - __bfloat162float(h0));
    __nv_bfloat16 l1 = __float2bfloat16_rn(f1 - __bfloat162float(h1));
    hi = (uint32_t)__bfloat16_as_ushort(h0) | ((uint32_t)__bfloat16_as_ushort(h1) << 16);
    lo = (uint32_t)__bfloat16_as_ushort(l0) | ((uint32_t)__bfloat16_as_ushort(l1) << 16);
}

// m16n8k16 bf16 MMA, D += A*B (D==C in-place)
__device__ __forceinline__ void mma16816(float* d, const uint32_t* a, const uint32_t* b) {
    asm volatile(
        "mma.sync.aligned.m16n8k16.row.col.f32.bf16.bf16.f32 "
        "{%0,%1,%2,%3}, {%4,%5,%6,%7}, {%8,%9}, {%0,%1,%2,%3};"
        : "+f"(d[0]), "+f"(d[1]), "+f"(d[2]), "+f"(d[3])
        : "r"(a[0]), "r"(a[1]), "r"(a[2]), "r"(a[3]), "r"(b[0]), "r"(b[1]));
}

// smem row stride for bf16-pair tiles: 20 u32 = 40 bf16 = 80 B
// bank(r,c) = (20r + c) mod 32 -> conflict-free for the quad access pattern.
#define PSTR 20

// ---------------------------------------------------------------------------
// CSR build: degree count -> 3-pass scan -> placement; also dinv.
// ---------------------------------------------------------------------------
__global__ void k_zero_deg(int N) {
    int i = blockIdx.x * blockDim.x + threadIdx.x;
    if (i < N) g_deg[i] = 0;
}
__global__ void k_count(const int* __restrict__ col, int E) {
    int e = blockIdx.x * blockDim.x + threadIdx.x;
    if (e < E) atomicAdd(&g_deg[col[e]], 1);
}
__global__ __launch_bounds__(SCAN_BLK) void k_scan_block(int N) {
    __shared__ int s[SCAN_BLK];
    int t = threadIdx.x;
    int i = blockIdx.x * SCAN_BLK + t;
    int v = (i < N) ? g_deg[i] : 0;
    s[t] = v;
    __syncthreads();
#pragma unroll
    for (int d = 1; d < SCAN_BLK; d <<= 1) {
        int x = s[t];
        if (t >= d) x += s[t - d];
        __syncthreads();
        s[t] = x;
        __syncthreads();
    }
    if (i < N) g_off[i] = s[t] - v;
    if (t == SCAN_BLK - 1) g_bsum[blockIdx.x] = s[t];
}
__global__ __launch_bounds__(128) void k_scan_tops(int nb) {
    __shared__ int s[128];
    int t = threadIdx.x;
    int v = (t < nb) ? g_bsum[t] : 0;
    s[t] = v;
    __syncthreads();
#pragma unroll
    for (int d = 1; d < 128; d <<= 1) {
        int x = s[t];
        if (t >= d) x += s[t - d];
        __syncthreads();
        s[t] = x;
        __syncthreads();
    }
    if (t < nb) g_bsum[t] = s[t] - v;
}
__global__ void k_scan_add(int N, int E) {
    int i = blockIdx.x * blockDim.x + threadIdx.x;
    if (i < N) {
        int o = g_off[i] + g_bsum[i / SCAN_BLK];
        g_off[i]    = o;
        g_cursor[i] = o;
        g_dinv[i]   = rsqrtf((float)g_deg[i] + 1.0f);
    }
    if (i == 0) g_off[N] = E;
}
__global__ void k_place(const int* __restrict__ row, const int* __restrict__ col, int E) {
    int e = blockIdx.x * blockDim.x + threadIdx.x;
    if (e < E) {
        int c = col[e];
        int p = atomicAdd(&g_cursor[c], 1);
        g_eidx[p] = row[e];
    }
}

// ---------------------------------------------------------------------------
// GEMM1 (mma.sync bf16-split): Hs = (X @ W1) * dinv[row]
// CTA 128x128, 8 warps in 2m x 4n (warp tile 64x32). K in 4 chunks of 32.
// ---------------------------------------------------------------------------
__global__ __launch_bounds__(256) void k_gemm1(
    const float* __restrict__ X, const float* __restrict__ W, int N)
{
    __shared__ uint32_t AsH[128 * PSTR], AsL[128 * PSTR];
    __shared__ uint32_t BsH[128 * PSTR], BsL[128 * PSTR];

    const int tid  = threadIdx.x;
    const int lane = tid & 31;
    const int wid  = tid >> 5;
    const int wm   = wid & 1;     // 2 warp rows of 64
    const int wn   = wid >> 1;    // 4 warp cols of 32
    const int bi   = blockIdx.x * 128;

    // loaders: thread -> (row, k-half of 16)
    const int ar  = tid >> 1;
    const int akh = (tid & 1) * 16;
    const int arc = min(bi + ar, N - 1);
    const float* Xrow = X + (size_t)arc * FIN;

    float acc[4][4][4];
#pragma unroll
    for (int mi = 0; mi < 4; mi++)
#pragma unroll
        for (int ni = 0; ni < 4; ni++)
#pragma unroll
            for (int q = 0; q < 4; q++) acc[mi][ni][q] = 0.f;

    for (int ch = 0; ch < 4; ch++) {
        const int kc = ch * 32;
        __syncthreads();   // previous chunk fully consumed
        // A convert: row ar, k = kc+akh .. +16
#pragma unroll
        for (int i = 0; i < 4; i++) {
            float4 v = *(const float4*)&Xrow[kc + akh + 4 * i];
            uint32_t h0, l0, h1, l1;
            split_pack(v.x, v.y, h0, l0);
            split_pack(v.z, v.w, h1, l1);
            int p = ar * PSTR + (akh >> 1) + 2 * i;
            AsH[p] = h0; AsH[p + 1] = h1;
            AsL[p] = l0; AsL[p + 1] = l1;
        }
        // B convert: B[n][k] = W[kc+k][n], n = ar
#pragma unroll
        for (int kk = 0; kk < 16; kk += 2) {
            float f0 = W[(size_t)(kc + akh + kk)     * FHID + ar];
            float f1 = W[(size_t)(kc + akh + kk + 1) * FHID + ar];
            uint32_t h, l;
            split_pack(f0, f1, h, l);
            int p = ar * PSTR + ((akh + kk) >> 1);
            BsH[p] = h;
            BsL[p] = l;
        }
        __syncthreads();

#pragma unroll
        for (int ks = 0; ks < 2; ks++) {
            const int pb = ks * 8;
            uint32_t bh[4][2], bl[4][2], afr[4][4];
#pragma unroll
            for (int ni = 0; ni < 4; ni++) {
                int idx = (wn * 32 + ni * 8 + (lane >> 2)) * PSTR + pb + (lane & 3);
                bh[ni][0] = BsH[idx]; bh[ni][1] = BsH[idx + 4];
                bl[ni][0] = BsL[idx]; bl[ni][1] = BsL[idx + 4];
            }
#pragma unroll
            for (int mi = 0; mi < 4; mi++) {
                int rb = wm * 64 + mi * 16 + (lane >> 2);
                int i0 = rb * PSTR + pb + (lane & 3);
                int i1 = i0 + 8 * PSTR;
                afr[mi][0] = AsH[i0]; afr[mi][1] = AsH[i1];
                afr[mi][2] = AsH[i0 + 4]; afr[mi][3] = AsH[i1 + 4];
            }
#pragma unroll
            for (int mi = 0; mi < 4; mi++)
#pragma unroll
                for (int ni = 0; ni < 4; ni++) {
                    mma16816(acc[mi][ni], afr[mi], bh[ni]);   // hi*hi
                    mma16816(acc[mi][ni], afr[mi], bl[ni]);   // hi*lo
                }
#pragma unroll
            for (int mi = 0; mi < 4; mi++) {
                int rb = wm * 64 + mi * 16 + (lane >> 2);
                int i0 = rb * PSTR + pb + (lane & 3);
                int i1 = i0 + 8 * PSTR;
                afr[mi][0] = AsL[i0]; afr[mi][1] = AsL[i1];
                afr[mi][2] = AsL[i0 + 4]; afr[mi][3] = AsL[i1 + 4];
            }
#pragma unroll
            for (int mi = 0; mi < 4; mi++)
#pragma unroll
                for (int ni = 0; ni < 4; ni++)
                    mma16816(acc[mi][ni], afr[mi], bh[ni]);   // lo*hi
        }
    }

    // epilogue: fused dinv scale
#pragma unroll
    for (int mi = 0; mi < 4; mi++) {
        int r0 = bi + wm * 64 + mi * 16 + (lane >> 2);
        int r1 = r0 + 8;
        float s0 = (r0 < N) ? g_dinv[r0] : 0.f;
        float s1 = (r1 < N) ? g_dinv[r1] : 0.f;
#pragma unroll
        for (int ni = 0; ni < 4; ni++) {
            int c = wn * 32 + ni * 8 + (lane & 3) * 2;
            if (r0 < N) {
                float2 v = make_float2(acc[mi][ni][0] * s0, acc[mi][ni][1] * s0);
                *(float2*)&g_Hs[(size_t)r0 * FHID + c] = v;
            }
            if (r1 < N) {
                float2 v = make_float2(acc[mi][ni][2] * s1, acc[mi][ni][3] * s1);
                *(float2*)&g_Hs[(size_t)r1 * FHID + c] = v;
            }
        }
    }
}

// ---------------------------------------------------------------------------
// GEMM2 (mma.sync bf16-split): Hs2 = (H2 @ W2) * dinv[row]
// CTA 128x64, 8 warps in 4m x 2n (warp tile 32x32). K in 4 chunks of 32.
// ---------------------------------------------------------------------------
__global__ __launch_bounds__(256) void k_gemm2(
    const float* __restrict__ W2, int N)
{
    __shared__ uint32_t AsH[128 * PSTR], AsL[128 * PSTR];
    __shared__ uint32_t BsH[64 * PSTR], BsL[64 * PSTR];

    const int tid  = threadIdx.x;
    const int lane = tid & 31;
    const int wid  = tid >> 5;
    const int wm   = wid & 3;     // 4 warp rows of 32
    const int wn   = wid >> 2;    // 2 warp cols of 32
    const int bi   = blockIdx.x * 128;

    const int ar  = tid >> 1;
    const int akh = (tid & 1) * 16;
    const int arc = min(bi + ar, N - 1);
    const float* Hrow = g_H2 + (size_t)arc * FHID;

    // B loader: n = tid>>2 (0..63), k-quarter = (tid&3)*8
    const int bn  = tid >> 2;
    const int bkq = (tid & 3) * 8;

    float acc[2][4][4];
#pragma unroll
    for (int mi = 0; mi < 2; mi++)
#pragma unroll
        for (int ni = 0; ni < 4; ni++)
#pragma unroll
            for (int q = 0; q < 4; q++) acc[mi][ni][q] = 0.f;

    for (int ch = 0; ch < 4; ch++) {
        const int kc = ch * 32;
        __syncthreads();
#pragma unroll
        for (int i = 0; i < 4; i++) {
            float4 v = *(const float4*)&Hrow[kc + akh + 4 * i];
            uint32_t h0, l0, h1, l1;
            split_pack(v.x, v.y, h0, l0);
            split_pack(v.z, v.w, h1, l1);
            int p = ar * PSTR + (akh >> 1) + 2 * i;
            AsH[p] = h0; AsH[p + 1] = h1;
            AsL[p] = l0; AsL[p + 1] = l1;
        }
#pragma unroll
        for (int kk = 0; kk < 8; kk += 2) {
            float f0 = W2[(size_t)(kc + bkq + kk)     * FOUT + bn];
            float f1 = W2[(size_t)(kc + bkq + kk + 1) * FOUT + bn];
            uint32_t h, l;
            split_pack(f0, f1, h, l);
            int p = bn * PSTR + ((bkq + kk) >> 1);
            BsH[p] = h;
            BsL[p] = l;
        }
        __syncthreads();

#pragma unroll
        for (int ks = 0; ks < 2; ks++) {
            const int pb = ks * 8;
            uint32_t bh[4][2], bl[4][2], afr[2][4];
#pragma unroll
            for (int ni = 0; ni < 4; ni++) {
                int idx = (wn * 32 + ni * 8 + (lane >> 2)) * PSTR + pb + (lane & 3);
                bh[ni][0] = BsH[idx]; bh[ni][1] = BsH[idx + 4];
                bl[ni][0] = BsL[idx]; bl[ni][1] = BsL[idx + 4];
            }
#pragma unroll
            for (int mi = 0; mi < 2; mi++) {
                int rb = wm * 32 + mi * 16 + (lane >> 2);
                int i0 = rb * PSTR + pb + (lane & 3);
                int i1 = i0 + 8 * PSTR;
                afr[mi][0] = AsH[i0]; afr[mi][1] = AsH[i1];
                afr[mi][2] = AsH[i0 + 4]; afr[mi][3] = AsH[i1 + 4];
            }
#pragma unroll
            for (int mi = 0; mi < 2; mi++)
#pragma unroll
                for (int ni = 0; ni < 4; ni++) {
                    mma16816(acc[mi][ni], afr[mi], bh[ni]);
                    mma16816(acc[mi][ni], afr[mi], bl[ni]);
                }
#pragma unroll
            for (int mi = 0; mi < 2; mi++) {
                int rb = wm * 32 + mi * 16 + (lane >> 2);
                int i0 = rb * PSTR + pb + (lane & 3);
                int i1 = i0 + 8 * PSTR;
                afr[mi][0] = AsL[i0]; afr[mi][1] = AsL[i1];
                afr[mi][2] = AsL[i0 + 4]; afr[mi][3] = AsL[i1 + 4];
            }
#pragma unroll
            for (int mi = 0; mi < 2; mi++)
#pragma unroll
                for (int ni = 0; ni < 4; ni++)
                    mma16816(acc[mi][ni], afr[mi], bh[ni]);
        }
    }

#pragma unroll
    for (int mi = 0; mi < 2; mi++) {
        int r0 = bi + wm * 32 + mi * 16 + (lane >> 2);
        int r1 = r0 + 8;
        float s0 = (r0 < N) ? g_dinv[r0] : 0.f;
        float s1 = (r1 < N) ? g_dinv[r1] : 0.f;
#pragma unroll
        for (int ni = 0; ni < 4; ni++) {
            int c = wn * 32 + ni * 8 + (lane & 3) * 2;
            if (r0 < N) {
                float2 v = make_float2(acc[mi][ni][0] * s0, acc[mi][ni][1] * s0);
                *(float2*)&g_Hs2[(size_t)r0 * FOUT + c] = v;
            }
            if (r1 < N) {
                float2 v = make_float2(acc[mi][ni][2] * s1, acc[mi][ni][3] * s1);
                *(float2*)&g_Hs2[(size_t)r1 * FOUT + c] = v;
            }
        }
    }
}

// ---------------------------------------------------------------------------
// Agg1 (CSR gather): one warp per node, lane = float4 of 128 feats.
// ---------------------------------------------------------------------------
__global__ __launch_bounds__(256) void k_agg1(const float* __restrict__ b1, int N) {
    int w    = (blockIdx.x * blockDim.x + threadIdx.x) >> 5;
    int lane = threadIdx.x & 31;
    if (w >= N) return;
    const float4* Hs4 = (const float4*)g_Hs;
    int beg = g_off[w], end = g_off[w + 1];

    float4 acc = Hs4[(size_t)w * 32 + lane];      // self-loop term
    for (int j0 = beg; j0 < end; j0 += 32) {
        int jj = j0 + lane;
        int myidx = (jj < end) ? g_eidx[jj] : 0;
        int m = min(32, end - j0);
        for (int t = 0; t < m; t++) {
            int r = __shfl_sync(0xffffffffu, myidx, t);
            float4 v = Hs4[(size_t)r * 32 + lane];
            acc.x += v.x; acc.y += v.y; acc.z += v.z; acc.w += v.w;
        }
    }
    float s = g_dinv[w];
    float4 bb = ((const float4*)b1)[lane];
    float4 o;
    o.x = fmaxf(fmaf(acc.x, s, bb.x), 0.f);
    o.y = fmaxf(fmaf(acc.y, s, bb.y), 0.f);
    o.z = fmaxf(fmaf(acc.z, s, bb.z), 0.f);
    o.w = fmaxf(fmaf(acc.w, s, bb.w), 0.f);
    ((float4*)g_H2)[(size_t)w * 32 + lane] = o;
}

// ---------------------------------------------------------------------------
// Agg2 (CSR gather): one warp per node, lane = float2 of 64 feats.
// ---------------------------------------------------------------------------
__global__ __launch_bounds__(256) void k_agg2(
    const float* __restrict__ b2, float* __restrict__ out, int N)
{
    int w    = (blockIdx.x * blockDim.x + threadIdx.x) >> 5;
    int lane = threadIdx.x & 31;
    if (w >= N) return;
    const float2* Hs2v = (const float2*)g_Hs2;
    int beg = g_off[w], end = g_off[w + 1];

    float2 acc = Hs2v[(size_t)w * 32 + lane];     // self-loop term
    for (int j0 = beg; j0 < end; j0 += 32) {
        int jj = j0 + lane;
        int myidx = (jj < end) ? g_eidx[jj] : 0;
        int m = min(32, end - j0);
        for (int t = 0; t < m; t++) {
            int r = __shfl_sync(0xffffffffu, myidx, t);
            float2 v = Hs2v[(size_t)r * 32 + lane];
            acc.x += v.x; acc.y += v.y;
        }
    }
    float s = g_dinv[w];
    float2 bb = ((const float2*)b2)[lane];
    float2 o;
    o.x = fmaf(acc.x, s, bb.x);
    o.y = fmaf(acc.y, s, bb.y);
    ((float2*)out)[(size_t)w * 32 + lane] = o;
}

// ---------------------------------------------------------------------------
// Launch
// ---------------------------------------------------------------------------
extern "C" void kernel_launch(void* const* d_in, const int* in_sizes, int n_in,
                              void* d_out, int out_size)
{
    const float* x  = (const float*)d_in[0];
    const int*   ei = (const int*)  d_in[1];
    const float* W1 = (const float*)d_in[2];
    const float* b1 = (const float*)d_in[3];
    const float* W2 = (const float*)d_in[4];
    const float* b2 = (const float*)d_in[5];
    float* out = (float*)d_out;

    const int N = in_sizes[0] / FIN;     // 100000
    const int E = in_sizes[1] / 2;       // 1600000
    const int* row = ei;
    const int* col = ei + E;

    const int nb = (N + SCAN_BLK - 1) / SCAN_BLK;

    // CSR build + dinv
    k_zero_deg  <<<(N + 255) / 256, 256>>>(N);
    k_count     <<<(E + 255) / 256, 256>>>(col, E);
    k_scan_block<<<nb, SCAN_BLK>>>(N);
    k_scan_tops <<<1, 128>>>(nb);
    k_scan_add  <<<(N + 255) / 256, 256>>>(N, E);
    k_place     <<<(E + 255) / 256, 256>>>(row, col, E);

    // Layer 1
    k_gemm1<<<(N + 127) / 128, 256>>>(x, W1, N);
    k_agg1 <<<(N * 32 + 255) / 256, 256>>>(b1, N);

    // Layer 2
    k_gemm2<<<(N + 127) / 128, 256>>>(W2, N);
    k_agg2 <<<(N * 32 + 255) / 256, 256>>>(b2, out, N);
}

// round 9
// speedup vs baseline: 1.7431x; 1.0461x over previous
#include <cuda_runtime.h>
#include <cuda_bf16.h>
#include <cuda_fp16.h>
#include <cstdint>

// Problem constants (reference: N=100000, E=1600000, IN=HID=128, OUT=64)
#define NMAX 100000
#define FIN  128
#define FHID 128
#define FOUT 64
#define SCAN_BLK 1024

// ---------------------------------------------------------------------------
// Device-global scratch (no allocation allowed)
// ---------------------------------------------------------------------------
__device__ int    g_deg[NMAX];
__device__ int    g_off[NMAX + 1];
__device__ int    g_cursor[NMAX];
__device__ int    g_bsum[128];
__device__ float  g_dinv[NMAX];
__device__ int    g_eidx[1600000];
__device__ __half g_Hsh [(size_t)NMAX * FHID]; // (X@W1) * dinv[row], fp16 messages
__device__ float  g_H2  [(size_t)NMAX * FHID]; // relu(dinv*agg1 + b1), fp32
__device__ __half g_Hs2h[(size_t)NMAX * FOUT]; // (H2@W2) * dinv[row], fp16 messages

// ---------------------------------------------------------------------------
// Helpers
// ---------------------------------------------------------------------------
__device__ __forceinline__ void split_pack(float f0, float f1, uint32_t& hi, uint32_t& lo) {
    __nv_bfloat16 h0 = __float2bfloat16_rn(f0);
    __nv_bfloat16 h1 = __float2bfloat16_rn(f1);
    __nv_bfloat16 l0 = __float2bfloat16_rn(f0 - __bfloat162float(h0));
    __nv_bfloat16 l1 = __float2bfloat16_rn(f1 - __bfloat162float(h1));
    hi = (uint32_t)__bfloat16_as_ushort(h0) | ((uint32_t)__bfloat16_as_ushort(h1) << 16);
    lo = (uint32_t)__bfloat16_as_ushort(l0) | ((uint32_t)__bfloat16_as_ushort(l1) << 16);
}

// m16n8k16 bf16 MMA, D += A*B (D==C in-place)
__device__ __forceinline__ void mma16816(float* d, const uint32_t* a, const uint32_t* b) {
    asm volatile(
        "mma.sync.aligned.m16n8k16.row.col.f32.bf16.bf16.f32 "
        "{%0,%1,%2,%3}, {%4,%5,%6,%7}, {%8,%9}, {%0,%1,%2,%3};"
        : "+f"(d[0]), "+f"(d[1]), "+f"(d[2]), "+f"(d[3])
        : "r"(a[0]), "r"(a[1]), "r"(a[2]), "r"(a[3]), "r"(b[0]), "r"(b[1]));
}

// smem row stride for bf16-pair tiles: 20 u32 = 40 bf16 = 80 B (conflict-free)
#define PSTR 20

// ---------------------------------------------------------------------------
// CSR build: degree count -> 3-pass scan -> placement; also dinv.
// ---------------------------------------------------------------------------
__global__ void k_zero_deg(int N) {
    int i = blockIdx.x * blockDim.x + threadIdx.x;
    if (i < N) g_deg[i] = 0;
}
__global__ void k_count(const int* __restrict__ col, int E) {
    int e = blockIdx.x * blockDim.x + threadIdx.x;
    if (e < E) atomicAdd(&g_deg[col[e]], 1);
}
__global__ __launch_bounds__(SCAN_BLK) void k_scan_block(int N) {
    __shared__ int s[SCAN_BLK];
    int t = threadIdx.x;
    int i = blockIdx.x * SCAN_BLK + t;
    int v = (i < N) ? g_deg[i] : 0;
    s[t] = v;
    __syncthreads();
#pragma unroll
    for (int d = 1; d < SCAN_BLK; d <<= 1) {
        int x = s[t];
        if (t >= d) x += s[t - d];
        __syncthreads();
        s[t] = x;
        __syncthreads();
    }
    if (i < N) g_off[i] = s[t] - v;
    if (t == SCAN_BLK - 1) g_bsum[blockIdx.x] = s[t];
}
__global__ __launch_bounds__(128) void k_scan_tops(int nb) {
    __shared__ int s[128];
    int t = threadIdx.x;
    int v = (t < nb) ? g_bsum[t] : 0;
    s[t] = v;
    __syncthreads();
#pragma unroll
    for (int d = 1; d < 128; d <<= 1) {
        int x = s[t];
        if (t >= d) x += s[t - d];
        __syncthreads();
        s[t] = x;
        __syncthreads();
    }
    if (t < nb) g_bsum[t] = s[t] - v;
}
__global__ void k_scan_add(int N, int E) {
    int i = blockIdx.x * blockDim.x + threadIdx.x;
    if (i < N) {
        int o = g_off[i] + g_bsum[i / SCAN_BLK];
        g_off[i]    = o;
        g_cursor[i] = o;
        g_dinv[i]   = rsqrtf((float)g_deg[i] + 1.0f);
    }
    if (i == 0) g_off[N] = E;
}
__global__ void k_place(const int* __restrict__ row, const int* __restrict__ col, int E) {
    int e = blockIdx.x * blockDim.x + threadIdx.x;
    if (e < E) {
        int c = col[e];
        int p = atomicAdd(&g_cursor[c], 1);
        g_eidx[p] = row[e];
    }
}

// ---------------------------------------------------------------------------
// GEMM1 (mma.sync bf16-split): Hsh = fp16((X @ W1) * dinv[row])
// CTA 128x128, 8 warps in 2m x 4n. K in 4 chunks of 32.
// ---------------------------------------------------------------------------
__global__ __launch_bounds__(256) void k_gemm1(
    const float* __restrict__ X, const float* __restrict__ W, int N)
{
    __shared__ uint32_t AsH[128 * PSTR], AsL[128 * PSTR];
    __shared__ uint32_t BsH[128 * PSTR], BsL[128 * PSTR];

    const int tid  = threadIdx.x;
    const int lane = tid & 31;
    const int wid  = tid >> 5;
    const int wm   = wid & 1;
    const int wn   = wid >> 1;
    const int bi   = blockIdx.x * 128;

    const int ar  = tid >> 1;
    const int akh = (tid & 1) * 16;
    const int arc = min(bi + ar, N - 1);
    const float* Xrow = X + (size_t)arc * FIN;

    float acc[4][4][4];
#pragma unroll
    for (int mi = 0; mi < 4; mi++)
#pragma unroll
        for (int ni = 0; ni < 4; ni++)
#pragma unroll
            for (int q = 0; q < 4; q++) acc[mi][ni][q] = 0.f;

    for (int ch = 0; ch < 4; ch++) {
        const int kc = ch * 32;
        __syncthreads();
#pragma unroll
        for (int i = 0; i < 4; i++) {
            float4 v = *(const float4*)&Xrow[kc + akh + 4 * i];
            uint32_t h0, l0, h1, l1;
            split_pack(v.x, v.y, h0, l0);
            split_pack(v.z, v.w, h1, l1);
            int p = ar * PSTR + (akh >> 1) + 2 * i;
            AsH[p] = h0; AsH[p + 1] = h1;
            AsL[p] = l0; AsL[p + 1] = l1;
        }
#pragma unroll
        for (int kk = 0; kk < 16; kk += 2) {
            float f0 = W[(size_t)(kc + akh + kk)     * FHID + ar];
            float f1 = W[(size_t)(kc + akh + kk + 1) * FHID + ar];
            uint32_t h, l;
            split_pack(f0, f1, h, l);
            int p = ar * PSTR + ((akh + kk) >> 1);
            BsH[p] = h;
            BsL[p] = l;
        }
        __syncthreads();

#pragma unroll
        for (int ks = 0; ks < 2; ks++) {
            const int pb = ks * 8;
            uint32_t bh[4][2], bl[4][2], afr[4][4];
#pragma unroll
            for (int ni = 0; ni < 4; ni++) {
                int idx = (wn * 32 + ni * 8 + (lane >> 2)) * PSTR + pb + (lane & 3);
                bh[ni][0] = BsH[idx]; bh[ni][1] = BsH[idx + 4];
                bl[ni][0] = BsL[idx]; bl[ni][1] = BsL[idx + 4];
            }
#pragma unroll
            for (int mi = 0; mi < 4; mi++) {
                int rb = wm * 64 + mi * 16 + (lane >> 2);
                int i0 = rb * PSTR + pb + (lane & 3);
                int i1 = i0 + 8 * PSTR;
                afr[mi][0] = AsH[i0]; afr[mi][1] = AsH[i1];
                afr[mi][2] = AsH[i0 + 4]; afr[mi][3] = AsH[i1 + 4];
            }
#pragma unroll
            for (int mi = 0; mi < 4; mi++)
#pragma unroll
                for (int ni = 0; ni < 4; ni++) {
                    mma16816(acc[mi][ni], afr[mi], bh[ni]);   // hi*hi
                    mma16816(acc[mi][ni], afr[mi], bl[ni]);   // hi*lo
                }
#pragma unroll
            for (int mi = 0; mi < 4; mi++) {
                int rb = wm * 64 + mi * 16 + (lane >> 2);
                int i0 = rb * PSTR + pb + (lane & 3);
                int i1 = i0 + 8 * PSTR;
                afr[mi][0] = AsL[i0]; afr[mi][1] = AsL[i1];
                afr[mi][2] = AsL[i0 + 4]; afr[mi][3] = AsL[i1 + 4];
            }
#pragma unroll
            for (int mi = 0; mi < 4; mi++)
#pragma unroll
                for (int ni = 0; ni < 4; ni++)
                    mma16816(acc[mi][ni], afr[mi], bh[ni]);   // lo*hi
        }
    }

    // epilogue: fused dinv scale, fp16 store
#pragma unroll
    for (int mi = 0; mi < 4; mi++) {
        int r0 = bi + wm * 64 + mi * 16 + (lane >> 2);
        int r1 = r0 + 8;
        float s0 = (r0 < N) ? g_dinv[r0] : 0.f;
        float s1 = (r1 < N) ? g_dinv[r1] : 0.f;
#pragma unroll
        for (int ni = 0; ni < 4; ni++) {
            int c = wn * 32 + ni * 8 + (lane & 3) * 2;
            if (r0 < N) {
                __half2 v = __floats2half2_rn(acc[mi][ni][0] * s0, acc[mi][ni][1] * s0);
                *(__half2*)&g_Hsh[(size_t)r0 * FHID + c] = v;
            }
            if (r1 < N) {
                __half2 v = __floats2half2_rn(acc[mi][ni][2] * s1, acc[mi][ni][3] * s1);
                *(__half2*)&g_Hsh[(size_t)r1 * FHID + c] = v;
            }
        }
    }
}

// ---------------------------------------------------------------------------
// Agg1 (CSR gather, fp16 msgs): one warp per node, lane = 4 halves of 128 feats.
// acc = Hsh[v] + sum Hsh[src]; H2 = relu(dinv[v]*acc + b1)  (fp32 accumulate)
// ---------------------------------------------------------------------------
__global__ __launch_bounds__(256) void k_agg1(const float* __restrict__ b1, int N) {
    int w    = (blockIdx.x * blockDim.x + threadIdx.x) >> 5;
    int lane = threadIdx.x & 31;
    if (w >= N) return;
    int beg = g_off[w], end = g_off[w + 1];

    const __half2* self = (const __half2*)&g_Hsh[(size_t)w * FHID + lane * 4];
    float2 p0 = __half22float2(self[0]);
    float2 p1 = __half22float2(self[1]);
    float a0 = p0.x, a1 = p0.y, a2 = p1.x, a3 = p1.y;

    for (int j0 = beg; j0 < end; j0 += 32) {
        int jj = j0 + lane;
        int myidx = (jj < end) ? g_eidx[jj] : 0;
        int m = min(32, end - j0);
        for (int t = 0; t < m; t++) {
            int r = __shfl_sync(0xffffffffu, myidx, t);
            const __half2* src = (const __half2*)&g_Hsh[(size_t)r * FHID + lane * 4];
            float2 q0 = __half22float2(src[0]);
            float2 q1 = __half22float2(src[1]);
            a0 += q0.x; a1 += q0.y; a2 += q1.x; a3 += q1.y;
        }
    }
    float s = g_dinv[w];
    float4 bb = ((const float4*)b1)[lane];
    float4 o;
    o.x = fmaxf(fmaf(a0, s, bb.x), 0.f);
    o.y = fmaxf(fmaf(a1, s, bb.y), 0.f);
    o.z = fmaxf(fmaf(a2, s, bb.z), 0.f);
    o.w = fmaxf(fmaf(a3, s, bb.w), 0.f);
    ((float4*)g_H2)[(size_t)w * 32 + lane] = o;
}

// ---------------------------------------------------------------------------
// GEMM2 (mma.sync bf16-split): Hs2h = fp16((H2 @ W2) * dinv[row])
// CTA 128x64, 8 warps in 4m x 2n. K in 4 chunks of 32.
// ---------------------------------------------------------------------------
__global__ __launch_bounds__(256) void k_gemm2(
    const float* __restrict__ W2, int N)
{
    __shared__ uint32_t AsH[128 * PSTR], AsL[128 * PSTR];
    __shared__ uint32_t BsH[64 * PSTR], BsL[64 * PSTR];

    const int tid  = threadIdx.x;
    const int lane = tid & 31;
    const int wid  = tid >> 5;
    const int wm   = wid & 3;
    const int wn   = wid >> 2;
    const int bi   = blockIdx.x * 128;

    const int ar  = tid >> 1;
    const int akh = (tid & 1) * 16;
    const int arc = min(bi + ar, N - 1);
    const float* Hrow = g_H2 + (size_t)arc * FHID;

    const int bn  = tid >> 2;
    const int bkq = (tid & 3) * 8;

    float acc[2][4][4];
#pragma unroll
    for (int mi = 0; mi < 2; mi++)
#pragma unroll
        for (int ni = 0; ni < 4; ni++)
#pragma unroll
            for (int q = 0; q < 4; q++) acc[mi][ni][q] = 0.f;

    for (int ch = 0; ch < 4; ch++) {
        const int kc = ch * 32;
        __syncthreads();
#pragma unroll
        for (int i = 0; i < 4; i++) {
            float4 v = *(const float4*)&Hrow[kc + akh + 4 * i];
            uint32_t h0, l0, h1, l1;
            split_pack(v.x, v.y, h0, l0);
            split_pack(v.z, v.w, h1, l1);
            int p = ar * PSTR + (akh >> 1) + 2 * i;
            AsH[p] = h0; AsH[p + 1] = h1;
            AsL[p] = l0; AsL[p + 1] = l1;
        }
#pragma unroll
        for (int kk = 0; kk < 8; kk += 2) {
            float f0 = W2[(size_t)(kc + bkq + kk)     * FOUT + bn];
            float f1 = W2[(size_t)(kc + bkq + kk + 1) * FOUT + bn];
            uint32_t h, l;
            split_pack(f0, f1, h, l);
            int p = bn * PSTR + ((bkq + kk) >> 1);
            BsH[p] = h;
            BsL[p] = l;
        }
        __syncthreads();

#pragma unroll
        for (int ks = 0; ks < 2; ks++) {
            const int pb = ks * 8;
            uint32_t bh[4][2], bl[4][2], afr[2][4];
#pragma unroll
            for (int ni = 0; ni < 4; ni++) {
                int idx = (wn * 32 + ni * 8 + (lane >> 2)) * PSTR + pb + (lane & 3);
                bh[ni][0] = BsH[idx]; bh[ni][1] = BsH[idx + 4];
                bl[ni][0] = BsL[idx]; bl[ni][1] = BsL[idx + 4];
            }
#pragma unroll
            for (int mi = 0; mi < 2; mi++) {
                int rb = wm * 32 + mi * 16 + (lane >> 2);
                int i0 = rb * PSTR + pb + (lane & 3);
                int i1 = i0 + 8 * PSTR;
                afr[mi][0] = AsH[i0]; afr[mi][1] = AsH[i1];
                afr[mi][2] = AsH[i0 + 4]; afr[mi][3] = AsH[i1 + 4];
            }
#pragma unroll
            for (int mi = 0; mi < 2; mi++)
#pragma unroll
                for (int ni = 0; ni < 4; ni++) {
                    mma16816(acc[mi][ni], afr[mi], bh[ni]);
                    mma16816(acc[mi][ni], afr[mi], bl[ni]);
                }
#pragma unroll
            for (int mi = 0; mi < 2; mi++) {
                int rb = wm * 32 + mi * 16 + (lane >> 2);
                int i0 = rb * PSTR + pb + (lane & 3);
                int i1 = i0 + 8 * PSTR;
                afr[mi][0] = AsL[i0]; afr[mi][1] = AsL[i1];
                afr[mi][2] = AsL[i0 + 4]; afr[mi][3] = AsL[i1 + 4];
            }
#pragma unroll
            for (int mi = 0; mi < 2; mi++)
#pragma unroll
                for (int ni = 0; ni < 4; ni++)
                    mma16816(acc[mi][ni], afr[mi], bh[ni]);
        }
    }

#pragma unroll
    for (int mi = 0; mi < 2; mi++) {
        int r0 = bi + wm * 32 + mi * 16 + (lane >> 2);
        int r1 = r0 + 8;
        float s0 = (r0 < N) ? g_dinv[r0] : 0.f;
        float s1 = (r1 < N) ? g_dinv[r1] : 0.f;
#pragma unroll
        for (int ni = 0; ni < 4; ni++) {
            int c = wn * 32 + ni * 8 + (lane & 3) * 2;
            if (r0 < N) {
                __half2 v = __floats2half2_rn(acc[mi][ni][0] * s0, acc[mi][ni][1] * s0);
                *(__half2*)&g_Hs2h[(size_t)r0 * FOUT + c] = v;
            }
            if (r1 < N) {
                __half2 v = __floats2half2_rn(acc[mi][ni][2] * s1, acc[mi][ni][3] * s1);
                *(__half2*)&g_Hs2h[(size_t)r1 * FOUT + c] = v;
            }
        }
    }
}

// ---------------------------------------------------------------------------
// Agg2 (CSR gather, fp16 msgs): one warp per node, lane = half2 of 64 feats.
// out = dinv[v]*(Hs2h[v] + sum Hs2h[src]) + b2  (fp32 accumulate)
// ---------------------------------------------------------------------------
__global__ __launch_bounds__(256) void k_agg2(
    const float* __restrict__ b2, float* __restrict__ out, int N)
{
    int w    = (blockIdx.x * blockDim.x + threadIdx.x) >> 5;
    int lane = threadIdx.x & 31;
    if (w >= N) return;
    int beg = g_off[w], end = g_off[w + 1];

    float2 acc = __half22float2(*(const __half2*)&g_Hs2h[(size_t)w * FOUT + lane * 2]);

    for (int j0 = beg; j0 < end; j0 += 32) {
        int jj = j0 + lane;
        int myidx = (jj < end) ? g_eidx[jj] : 0;
        int m = min(32, end - j0);
        for (int t = 0; t < m; t++) {
            int r = __shfl_sync(0xffffffffu, myidx, t);
            float2 v = __half22float2(*(const __half2*)&g_Hs2h[(size_t)r * FOUT + lane * 2]);
            acc.x += v.x; acc.y += v.y;
        }
    }
    float s = g_dinv[w];
    float2 bb = ((const float2*)b2)[lane];
    float2 o;
    o.x = fmaf(acc.x, s, bb.x);
    o.y = fmaf(acc.y, s, bb.y);
    ((float2*)out)[(size_t)w * 32 + lane] = o;
}

// ---------------------------------------------------------------------------
// Launch
// ---------------------------------------------------------------------------
extern "C" void kernel_launch(void* const* d_in, const int* in_sizes, int n_in,
                              void* d_out, int out_size)
{
    const float* x  = (const float*)d_in[0];
    const int*   ei = (const int*)  d_in[1];
    const float* W1 = (const float*)d_in[2];
    const float* b1 = (const float*)d_in[3];
    const float* W2 = (const float*)d_in[4];
    const float* b2 = (const float*)d_in[5];
    float* out = (float*)d_out;

    const int N = in_sizes[0] / FIN;     // 100000
    const int E = in_sizes[1] / 2;       // 1600000
    const int* row = ei;
    const int* col = ei + E;

    const int nb = (N + SCAN_BLK - 1) / SCAN_BLK;

    // CSR build + dinv
    k_zero_deg  <<<(N + 255) / 256, 256>>>(N);
    k_count     <<<(E + 255) / 256, 256>>>(col, E);
    k_scan_block<<<nb, SCAN_BLK>>>(N);
    k_scan_tops <<<1, 128>>>(nb);
    k_scan_add  <<<(N + 255) / 256, 256>>>(N, E);
    k_place     <<<(E + 255) / 256, 256>>>(row, col, E);

    // Layer 1
    k_gemm1<<<(N + 127) / 128, 256>>>(x, W1, N);
    k_agg1 <<<(N * 32 + 255) / 256, 256>>>(b1, N);

    // Layer 2
    k_gemm2<<<(N + 127) / 128, 256>>>(W2, N);
    k_agg2 <<<(N * 32 + 255) / 256, 256>>>(b2, out, N);
}

// round 12
// speedup vs baseline: 1.8408x; 1.0561x over previous
#include <cuda_runtime.h>
#include <cuda_bf16.h>
#include <cuda_fp16.h>
#include <cstdint>

// Problem constants (reference: N=100000, E=1600000, IN=HID=128, OUT=64)
#define NMAX 100000
#define FIN  128
#define FHID 128
#define FOUT 64
#define SCAN_BLK 1024

// ---------------------------------------------------------------------------
// Device-global scratch (no allocation allowed)
// ---------------------------------------------------------------------------
__device__ int      g_deg[NMAX];
__device__ int      g_off[NMAX + 1];
__device__ int      g_cursor[NMAX];
__device__ int      g_bsum[128];
__device__ float    g_dinv[NMAX];
__device__ int      g_eidx[1600000];
__device__ __half   g_Hsh [(size_t)NMAX * FHID]; // (X@W1) * dinv[row], fp16 messages
__device__ float    g_H2  [(size_t)NMAX * FHID]; // relu(dinv*agg1 + b1), fp32
__device__ __half   g_Hs2h[(size_t)NMAX * FOUT]; // (H2@W2) * dinv[row], fp16 messages
// packed split weights: [n][pair] with pair = k/2 (even k in low half)
__device__ uint32_t g_W1h[128 * 64], g_W1l[128 * 64];
__device__ uint32_t g_W2h[64 * 64],  g_W2l[64 * 64];

// ---------------------------------------------------------------------------
// Helpers
// ---------------------------------------------------------------------------
__device__ __forceinline__ void split_pack(float f0, float f1, uint32_t& hi, uint32_t& lo) {
    __nv_bfloat16 h0 = __float2bfloat16_rn(f0);
    __nv_bfloat16 h1 = __float2bfloat16_rn(f1);
    __nv_bfloat16 l0 = __float2bfloat16_rn(f0 - __bfloat162float(h0));
    __nv_bfloat16 l1 = __float2bfloat16_rn(f1 - __bfloat162float(h1));
    hi = (uint32_t)__bfloat16_as_ushort(h0) | ((uint32_t)__bfloat16_as_ushort(h1) << 16);
    lo = (uint32_t)__bfloat16_as_ushort(l0) | ((uint32_t)__bfloat16_as_ushort(l1) << 16);
}

// m16n8k16 bf16 MMA, D += A*B (D==C in-place)
__device__ __forceinline__ void mma16816(float* d, const uint32_t* a, const uint32_t* b) {
    asm volatile(
        "mma.sync.aligned.m16n8k16.row.col.f32.bf16.bf16.f32 "
        "{%0,%1,%2,%3}, {%4,%5,%6,%7}, {%8,%9}, {%0,%1,%2,%3};"
        : "+f"(d[0]), "+f"(d[1]), "+f"(d[2]), "+f"(d[3])
        : "r"(a[0]), "r"(a[1]), "r"(a[2]), "r"(a[3]), "r"(b[0]), "r"(b[1]));
}

// smem row stride for bf16-pair tiles: 20 u32 = 40 bf16 = 80 B (conflict-free frags)
#define PSTR 20

// ---------------------------------------------------------------------------
// Pack W1/W2 into bf16 hi/lo pairs (once per launch; replaces per-CTA convert)
// ---------------------------------------------------------------------------
__global__ void k_packw(const float* __restrict__ W1, const float* __restrict__ W2) {
    int i = blockIdx.x * blockDim.x + threadIdx.x;
    if (i < 128 * 64) {
        int n = i >> 6, p = (i & 63) * 2;
        uint32_t h, l;
        split_pack(W1[(size_t)p * FHID + n], W1[(size_t)(p + 1) * FHID + n], h, l);
        g_W1h[i] = h; g_W1l[i] = l;
    } else if (i < 128 * 64 + 64 * 64) {
        int j = i - 128 * 64;
        int n = j >> 6, p = (j & 63) * 2;
        uint32_t h, l;
        split_pack(W2[(size_t)p * FOUT + n], W2[(size_t)(p + 1) * FOUT + n], h, l);
        g_W2h[j] = h; g_W2l[j] = l;
    }
}

// ---------------------------------------------------------------------------
// CSR build: degree count -> 3-pass scan -> placement; also dinv.
// ---------------------------------------------------------------------------
__global__ void k_zero_deg(int N) {
    int i = blockIdx.x * blockDim.x + threadIdx.x;
    if (i < N) g_deg[i] = 0;
}
__global__ void k_count(const int* __restrict__ col, int E) {
    int e = blockIdx.x * blockDim.x + threadIdx.x;
    if (e < E) atomicAdd(&g_deg[col[e]], 1);
}
__global__ __launch_bounds__(SCAN_BLK) void k_scan_block(int N) {
    __shared__ int s[SCAN_BLK];
    int t = threadIdx.x;
    int i = blockIdx.x * SCAN_BLK + t;
    int v = (i < N) ? g_deg[i] : 0;
    s[t] = v;
    __syncthreads();
#pragma unroll
    for (int d = 1; d < SCAN_BLK; d <<= 1) {
        int x = s[t];
        if (t >= d) x += s[t - d];
        __syncthreads();
        s[t] = x;
        __syncthreads();
    }
    if (i < N) g_off[i] = s[t] - v;
    if (t == SCAN_BLK - 1) g_bsum[blockIdx.x] = s[t];
}
__global__ __launch_bounds__(128) void k_scan_tops(int nb) {
    __shared__ int s[128];
    int t = threadIdx.x;
    int v = (t < nb) ? g_bsum[t] : 0;
    s[t] = v;
    __syncthreads();
#pragma unroll
    for (int d = 1; d < 128; d <<= 1) {
        int x = s[t];
        if (t >= d) x += s[t - d];
        __syncthreads();
        s[t] = x;
        __syncthreads();
    }
    if (t < nb) g_bsum[t] = s[t] - v;
}
__global__ void k_scan_add(int N, int E) {
    int i = blockIdx.x * blockDim.x + threadIdx.x;
    if (i < N) {
        int o = g_off[i] + g_bsum[i / SCAN_BLK];
        g_off[i]    = o;
        g_cursor[i] = o;
        g_dinv[i]   = rsqrtf((float)g_deg[i] + 1.0f);
    }
    if (i == 0) g_off[N] = E;
}
__global__ void k_place(const int* __restrict__ row, const int* __restrict__ col, int E) {
    int e = blockIdx.x * blockDim.x + threadIdx.x;
    if (e < E) {
        int c = col[e];
        int p = atomicAdd(&g_cursor[c], 1);
        g_eidx[p] = row[e];
    }
}

// ---------------------------------------------------------------------------
// GEMM1 (mma.sync bf16-split): Hsh = fp16((X @ W1) * dinv[row])
// CTA 128x128, 8 warps in 2m x 4n. K in 4 chunks of 32. B from packed weights.
// ---------------------------------------------------------------------------
__global__ __launch_bounds__(256) void k_gemm1(
    const float* __restrict__ X, int N)
{
    __shared__ uint32_t AsH[128 * PSTR], AsL[128 * PSTR];
    __shared__ uint32_t BsH[128 * PSTR], BsL[128 * PSTR];

    const int tid  = threadIdx.x;
    const int lane = tid & 31;
    const int wid  = tid >> 5;
    const int wm   = wid & 1;
    const int wn   = wid >> 1;
    const int bi   = blockIdx.x * 128;

    const int ar  = tid >> 1;
    const int akh = (tid & 1) * 16;
    const int arc = min(bi + ar, N - 1);
    const float* Xrow = X + (size_t)arc * FIN;

    // B loader: n = tid>>1 (0..127), 8 pairs starting at (tid&1)*8
    const int bn  = tid >> 1;
    const int bp0 = (tid & 1) * 8;

    float acc[4][4][4];
#pragma unroll
    for (int mi = 0; mi < 4; mi++)
#pragma unroll
        for (int ni = 0; ni < 4; ni++)
#pragma unroll
            for (int q = 0; q < 4; q++) acc[mi][ni][q] = 0.f;

    for (int ch = 0; ch < 4; ch++) {
        const int kc = ch * 32;
        const int cp = ch * 16;               // global pair base
        __syncthreads();
        // A convert: row ar, k = kc+akh .. +16
#pragma unroll
        for (int i = 0; i < 4; i++) {
            float4 v = *(const float4*)&Xrow[kc + akh + 4 * i];
            uint32_t h0, l0, h1, l1;
            split_pack(v.x, v.y, h0, l0);
            split_pack(v.z, v.w, h1, l1);
            int p = ar * PSTR + (akh >> 1) + 2 * i;
            AsH[p] = h0; AsH[p + 1] = h1;
            AsL[p] = l0; AsL[p + 1] = l1;
        }
        // B: direct copy of packed weights (8 pairs = 2 uint4 per array)
        {
            uint4 h0 = *(const uint4*)&g_W1h[bn * 64 + cp + bp0];
            uint4 h1 = *(const uint4*)&g_W1h[bn * 64 + cp + bp0 + 4];
            uint4 l0 = *(const uint4*)&g_W1l[bn * 64 + cp + bp0];
            uint4 l1 = *(const uint4*)&g_W1l[bn * 64 + cp + bp0 + 4];
            *(uint4*)&BsH[bn * PSTR + bp0]     = h0;
            *(uint4*)&BsH[bn * PSTR + bp0 + 4] = h1;
            *(uint4*)&BsL[bn * PSTR + bp0]     = l0;
            *(uint4*)&BsL[bn * PSTR + bp0 + 4] = l1;
        }
        __syncthreads();

#pragma unroll
        for (int ks = 0; ks < 2; ks++) {
            const int pb = ks * 8;
            uint32_t bh[4][2], bl[4][2], afr[4][4];
#pragma unroll
            for (int ni = 0; ni < 4; ni++) {
                int idx = (wn * 32 + ni * 8 + (lane >> 2)) * PSTR + pb + (lane & 3);
                bh[ni][0] = BsH[idx]; bh[ni][1] = BsH[idx + 4];
                bl[ni][0] = BsL[idx]; bl[ni][1] = BsL[idx + 4];
            }
#pragma unroll
            for (int mi = 0; mi < 4; mi++) {
                int rb = wm * 64 + mi * 16 + (lane >> 2);
                int i0 = rb * PSTR + pb + (lane & 3);
                int i1 = i0 + 8 * PSTR;
                afr[mi][0] = AsH[i0]; afr[mi][1] = AsH[i1];
                afr[mi][2] = AsH[i0 + 4]; afr[mi][3] = AsH[i1 + 4];
            }
#pragma unroll
            for (int mi = 0; mi < 4; mi++)
#pragma unroll
                for (int ni = 0; ni < 4; ni++) {
                    mma16816(acc[mi][ni], afr[mi], bh[ni]);   // hi*hi
                    mma16816(acc[mi][ni], afr[mi], bl[ni]);   // hi*lo
                }
#pragma unroll
            for (int mi = 0; mi < 4; mi++) {
                int rb = wm * 64 + mi * 16 + (lane >> 2);
                int i0 = rb * PSTR + pb + (lane & 3);
                int i1 = i0 + 8 * PSTR;
                afr[mi][0] = AsL[i0]; afr[mi][1] = AsL[i1];
                afr[mi][2] = AsL[i0 + 4]; afr[mi][3] = AsL[i1 + 4];
            }
#pragma unroll
            for (int mi = 0; mi < 4; mi++)
#pragma unroll
                for (int ni = 0; ni < 4; ni++)
                    mma16816(acc[mi][ni], afr[mi], bh[ni]);   // lo*hi
        }
    }

    // epilogue: fused dinv scale, fp16 store
#pragma unroll
    for (int mi = 0; mi < 4; mi++) {
        int r0 = bi + wm * 64 + mi * 16 + (lane >> 2);
        int r1 = r0 + 8;
        float s0 = (r0 < N) ? g_dinv[r0] : 0.f;
        float s1 = (r1 < N) ? g_dinv[r1] : 0.f;
#pragma unroll
        for (int ni = 0; ni < 4; ni++) {
            int c = wn * 32 + ni * 8 + (lane & 3) * 2;
            if (r0 < N) {
                __half2 v = __floats2half2_rn(acc[mi][ni][0] * s0, acc[mi][ni][1] * s0);
                *(__half2*)&g_Hsh[(size_t)r0 * FHID + c] = v;
            }
            if (r1 < N) {
                __half2 v = __floats2half2_rn(acc[mi][ni][2] * s1, acc[mi][ni][3] * s1);
                *(__half2*)&g_Hsh[(size_t)r1 * FHID + c] = v;
            }
        }
    }
}

// ---------------------------------------------------------------------------
// Agg1 (CSR gather, fp16, MLP=4): one warp per node, lane = 4 halves (8 B).
// ---------------------------------------------------------------------------
__global__ __launch_bounds__(256) void k_agg1(const float* __restrict__ b1, int N) {
    int w    = (blockIdx.x * blockDim.x + threadIdx.x) >> 5;
    int lane = threadIdx.x & 31;
    if (w >= N) return;
    int beg = g_off[w], end = g_off[w + 1];

    const uint2 su = *(const uint2*)&g_Hsh[(size_t)w * FHID + lane * 4];
    float2 p0 = __half22float2(*(const __half2*)&su.x);
    float2 p1 = __half22float2(*(const __half2*)&su.y);
    float a0 = p0.x, a1 = p0.y, a2 = p1.x, a3 = p1.y;

    for (int j0 = beg; j0 < end; j0 += 32) {
        int jj = j0 + lane;
        int myidx = (jj < end) ? g_eidx[jj] : 0;
        int m = min(32, end - j0);
        int t = 0;
        for (; t + 4 <= m; t += 4) {
            int r0 = __shfl_sync(0xffffffffu, myidx, t);
            int r1 = __shfl_sync(0xffffffffu, myidx, t + 1);
            int r2 = __shfl_sync(0xffffffffu, myidx, t + 2);
            int r3 = __shfl_sync(0xffffffffu, myidx, t + 3);
            uint2 u0 = *(const uint2*)&g_Hsh[(size_t)r0 * FHID + lane * 4];
            uint2 u1 = *(const uint2*)&g_Hsh[(size_t)r1 * FHID + lane * 4];
            uint2 u2 = *(const uint2*)&g_Hsh[(size_t)r2 * FHID + lane * 4];
            uint2 u3 = *(const uint2*)&g_Hsh[(size_t)r3 * FHID + lane * 4];
            float2 q;
            q = __half22float2(*(const __half2*)&u0.x); a0 += q.x; a1 += q.y;
            q = __half22float2(*(const __half2*)&u0.y); a2 += q.x; a3 += q.y;
            q = __half22float2(*(const __half2*)&u1.x); a0 += q.x; a1 += q.y;
            q = __half22float2(*(const __half2*)&u1.y); a2 += q.x; a3 += q.y;
            q = __half22float2(*(const __half2*)&u2.x); a0 += q.x; a1 += q.y;
            q = __half22float2(*(const __half2*)&u2.y); a2 += q.x; a3 += q.y;
            q = __half22float2(*(const __half2*)&u3.x); a0 += q.x; a1 += q.y;
            q = __half22float2(*(const __half2*)&u3.y); a2 += q.x; a3 += q.y;
        }
        for (; t < m; t++) {
            int r = __shfl_sync(0xffffffffu, myidx, t);
            uint2 u = *(const uint2*)&g_Hsh[(size_t)r * FHID + lane * 4];
            float2 q;
            q = __half22float2(*(const __half2*)&u.x); a0 += q.x; a1 += q.y;
            q = __half22float2(*(const __half2*)&u.y); a2 += q.x; a3 += q.y;
        }
    }
    float s = g_dinv[w];
    float4 bb = ((const float4*)b1)[lane];
    float4 o;
    o.x = fmaxf(fmaf(a0, s, bb.x), 0.f);
    o.y = fmaxf(fmaf(a1, s, bb.y), 0.f);
    o.z = fmaxf(fmaf(a2, s, bb.z), 0.f);
    o.w = fmaxf(fmaf(a3, s, bb.w), 0.f);
    ((float4*)g_H2)[(size_t)w * 32 + lane] = o;
}

// ---------------------------------------------------------------------------
// GEMM2 (mma.sync bf16-split): Hs2h = fp16((H2 @ W2) * dinv[row])
// CTA 128x64, 8 warps in 4m x 2n. K in 4 chunks of 32. B from packed weights.
// ---------------------------------------------------------------------------
__global__ __launch_bounds__(256) void k_gemm2(int N)
{
    __shared__ uint32_t AsH[128 * PSTR], AsL[128 * PSTR];
    __shared__ uint32_t BsH[64 * PSTR], BsL[64 * PSTR];

    const int tid  = threadIdx.x;
    const int lane = tid & 31;
    const int wid  = tid >> 5;
    const int wm   = wid & 3;
    const int wn   = wid >> 2;
    const int bi   = blockIdx.x * 128;

    const int ar  = tid >> 1;
    const int akh = (tid & 1) * 16;
    const int arc = min(bi + ar, N - 1);
    const float* Hrow = g_H2 + (size_t)arc * FHID;

    // B loader: n = tid>>2 (0..63), 4 pairs starting at (tid&3)*4
    const int bn  = tid >> 2;
    const int bp0 = (tid & 3) * 4;

    float acc[2][4][4];
#pragma unroll
    for (int mi = 0; mi < 2; mi++)
#pragma unroll
        for (int ni = 0; ni < 4; ni++)
#pragma unroll
            for (int q = 0; q < 4; q++) acc[mi][ni][q] = 0.f;

    for (int ch = 0; ch < 4; ch++) {
        const int kc = ch * 32;
        const int cp = ch * 16;
        __syncthreads();
#pragma unroll
        for (int i = 0; i < 4; i++) {
            float4 v = *(const float4*)&Hrow[kc + akh + 4 * i];
            uint32_t h0, l0, h1, l1;
            split_pack(v.x, v.y, h0, l0);
            split_pack(v.z, v.w, h1, l1);
            int p = ar * PSTR + (akh >> 1) + 2 * i;
            AsH[p] = h0; AsH[p + 1] = h1;
            AsL[p] = l0; AsL[p + 1] = l1;
        }
        {
            uint4 h = *(const uint4*)&g_W2h[bn * 64 + cp + bp0];
            uint4 l = *(const uint4*)&g_W2l[bn * 64 + cp + bp0];
            *(uint4*)&BsH[bn * PSTR + bp0] = h;
            *(uint4*)&BsL[bn * PSTR + bp0] = l;
        }
        __syncthreads();

#pragma unroll
        for (int ks = 0; ks < 2; ks++) {
            const int pb = ks * 8;
            uint32_t bh[4][2], bl[4][2], afr[2][4];
#pragma unroll
            for (int ni = 0; ni < 4; ni++) {
                int idx = (wn * 32 + ni * 8 + (lane >> 2)) * PSTR + pb + (lane & 3);
                bh[ni][0] = BsH[idx]; bh[ni][1] = BsH[idx + 4];
                bl[ni][0] = BsL[idx]; bl[ni][1] = BsL[idx + 4];
            }
#pragma unroll
            for (int mi = 0; mi < 2; mi++) {
                int rb = wm * 32 + mi * 16 + (lane >> 2);
                int i0 = rb * PSTR + pb + (lane & 3);
                int i1 = i0 + 8 * PSTR;
                afr[mi][0] = AsH[i0]; afr[mi][1] = AsH[i1];
                afr[mi][2] = AsH[i0 + 4]; afr[mi][3] = AsH[i1 + 4];
            }
#pragma unroll
            for (int mi = 0; mi < 2; mi++)
#pragma unroll
                for (int ni = 0; ni < 4; ni++) {
                    mma16816(acc[mi][ni], afr[mi], bh[ni]);
                    mma16816(acc[mi][ni], afr[mi], bl[ni]);
                }
#pragma unroll
            for (int mi = 0; mi < 2; mi++) {
                int rb = wm * 32 + mi * 16 + (lane >> 2);
                int i0 = rb * PSTR + pb + (lane & 3);
                int i1 = i0 + 8 * PSTR;
                afr[mi][0] = AsL[i0]; afr[mi][1] = AsL[i1];
                afr[mi][2] = AsL[i0 + 4]; afr[mi][3] = AsL[i1 + 4];
            }
#pragma unroll
            for (int mi = 0; mi < 2; mi++)
#pragma unroll
                for (int ni = 0; ni < 4; ni++)
                    mma16816(acc[mi][ni], afr[mi], bh[ni]);
        }
    }

#pragma unroll
    for (int mi = 0; mi < 2; mi++) {
        int r0 = bi + wm * 32 + mi * 16 + (lane >> 2);
        int r1 = r0 + 8;
        float s0 = (r0 < N) ? g_dinv[r0] : 0.f;
        float s1 = (r1 < N) ? g_dinv[r1] : 0.f;
#pragma unroll
        for (int ni = 0; ni < 4; ni++) {
            int c = wn * 32 + ni * 8 + (lane & 3) * 2;
            if (r0 < N) {
                __half2 v = __floats2half2_rn(acc[mi][ni][0] * s0, acc[mi][ni][1] * s0);
                *(__half2*)&g_Hs2h[(size_t)r0 * FOUT + c] = v;
            }
            if (r1 < N) {
                __half2 v = __floats2half2_rn(acc[mi][ni][2] * s1, acc[mi][ni][3] * s1);
                *(__half2*)&g_Hs2h[(size_t)r1 * FOUT + c] = v;
            }
        }
    }
}

// ---------------------------------------------------------------------------
// Agg2 (CSR gather, fp16, MLP=4): one warp per node, lane = half2 (4 B).
// ---------------------------------------------------------------------------
__global__ __launch_bounds__(256) void k_agg2(
    const float* __restrict__ b2, float* __restrict__ out, int N)
{
    int w    = (blockIdx.x * blockDim.x + threadIdx.x) >> 5;
    int lane = threadIdx.x & 31;
    if (w >= N) return;
    int beg = g_off[w], end = g_off[w + 1];

    float2 acc = __half22float2(*(const __half2*)&g_Hs2h[(size_t)w * FOUT + lane * 2]);

    for (int j0 = beg; j0 < end; j0 += 32) {
        int jj = j0 + lane;
        int myidx = (jj < end) ? g_eidx[jj] : 0;
        int m = min(32, end - j0);
        int t = 0;
        for (; t + 4 <= m; t += 4) {
            int r0 = __shfl_sync(0xffffffffu, myidx, t);
            int r1 = __shfl_sync(0xffffffffu, myidx, t + 1);
            int r2 = __shfl_sync(0xffffffffu, myidx, t + 2);
            int r3 = __shfl_sync(0xffffffffu, myidx, t + 3);
            uint32_t u0 = *(const uint32_t*)&g_Hs2h[(size_t)r0 * FOUT + lane * 2];
            uint32_t u1 = *(const uint32_t*)&g_Hs2h[(size_t)r1 * FOUT + lane * 2];
            uint32_t u2 = *(const uint32_t*)&g_Hs2h[(size_t)r2 * FOUT + lane * 2];
            uint32_t u3 = *(const uint32_t*)&g_Hs2h[(size_t)r3 * FOUT + lane * 2];
            float2 q;
            q = __half22float2(*(const __half2*)&u0); acc.x += q.x; acc.y += q.y;
            q = __half22float2(*(const __half2*)&u1); acc.x += q.x; acc.y += q.y;
            q = __half22float2(*(const __half2*)&u2); acc.x += q.x; acc.y += q.y;
            q = __half22float2(*(const __half2*)&u3); acc.x += q.x; acc.y += q.y;
        }
        for (; t < m; t++) {
            int r = __shfl_sync(0xffffffffu, myidx, t);
            uint32_t u = *(const uint32_t*)&g_Hs2h[(size_t)r * FOUT + lane * 2];
            float2 q = __half22float2(*(const __half2*)&u);
            acc.x += q.x; acc.y += q.y;
        }
    }
    float s = g_dinv[w];
    float2 bb = ((const float2*)b2)[lane];
    float2 o;
    o.x = fmaf(acc.x, s, bb.x);
    o.y = fmaf(acc.y, s, bb.y);
    ((float2*)out)[(size_t)w * 32 + lane] = o;
}

// ---------------------------------------------------------------------------
// Launch
// ---------------------------------------------------------------------------
extern "C" void kernel_launch(void* const* d_in, const int* in_sizes, int n_in,
                              void* d_out, int out_size)
{
    const float* x  = (const float*)d_in[0];
    const int*   ei = (const int*)  d_in[1];
    const float* W1 = (const float*)d_in[2];
    const float* b1 = (const float*)d_in[3];
    const float* W2 = (const float*)d_in[4];
    const float* b2 = (const float*)d_in[5];
    float* out = (float*)d_out;

    const int N = in_sizes[0] / FIN;     // 100000
    const int E = in_sizes[1] / 2;       // 1600000
    const int* row = ei;
    const int* col = ei + E;

    const int nb = (N + SCAN_BLK - 1) / SCAN_BLK;

    // Weight packing (independent of CSR build)
    k_packw<<<(128 * 64 + 64 * 64 + 255) / 256, 256>>>(W1, W2);

    // CSR build + dinv
    k_zero_deg  <<<(N + 255) / 256, 256>>>(N);
    k_count     <<<(E + 255) / 256, 256>>>(col, E);
    k_scan_block<<<nb, SCAN_BLK>>>(N);
    k_scan_tops <<<1, 128>>>(nb);
    k_scan_add  <<<(N + 255) / 256, 256>>>(N, E);
    k_place     <<<(E + 255) / 256, 256>>>(row, col, E);

    // Layer 1
    k_gemm1<<<(N + 127) / 128, 256>>>(x, N);
    k_agg1 <<<(N * 32 + 255) / 256, 256>>>(b1, N);

    // Layer 2
    k_gemm2<<<(N + 127) / 128, 256>>>(N);
    k_agg2 <<<(N * 32 + 255) / 256, 256>>>(b2, out, N);
}

// round 13
// speedup vs baseline: 1.8613x; 1.0111x over previous
#include <cuda_runtime.h>
#include <cuda_bf16.h>
#include <cuda_fp16.h>
#include <cstdint>

// Problem constants (reference: N=100000, E=1600000, IN=HID=128, OUT=64)
#define NMAX 100000
#define FIN  128
#define FHID 128
#define FOUT 64

// ---------------------------------------------------------------------------
// Device-global scratch (no allocation allowed)
// ---------------------------------------------------------------------------
__device__ int      g_deg[NMAX];
__device__ int      g_off[NMAX];               // segment start per node
__device__ int      g_cursor[NMAX];
__device__ int      g_total;                   // single-pass scan base counter
__device__ float    g_dinv[NMAX];
__device__ int      g_eidx[1600000];
__device__ __half   g_Hsh [(size_t)NMAX * FHID]; // X@W1 (UNSCALED), fp16 messages
__device__ float    g_H2  [(size_t)NMAX * FHID]; // relu(dinv*agg1 + b1), fp32
__device__ __half   g_Hs2h[(size_t)NMAX * FOUT]; // (H2@W2)*dinv[row], fp16 messages
// packed split weights: [n][pair] with pair = k/2
__device__ uint32_t g_W1h[128 * 64], g_W1l[128 * 64];
__device__ uint32_t g_W2h[64 * 64],  g_W2l[64 * 64];

// ---------------------------------------------------------------------------
// Helpers
// ---------------------------------------------------------------------------
__device__ __forceinline__ void split_pack(float f0, float f1, uint32_t& hi, uint32_t& lo) {
    __nv_bfloat16 h0 = __float2bfloat16_rn(f0);
    __nv_bfloat16 h1 = __float2bfloat16_rn(f1);
    __nv_bfloat16 l0 = __float2bfloat16_rn(f0 - __bfloat162float(h0));
    __nv_bfloat16 l1 = __float2bfloat16_rn(f1 - __bfloat162float(h1));
    hi = (uint32_t)__bfloat16_as_ushort(h0) | ((uint32_t)__bfloat16_as_ushort(h1) << 16);
    lo = (uint32_t)__bfloat16_as_ushort(l0) | ((uint32_t)__bfloat16_as_ushort(l1) << 16);
}

// m16n8k16 bf16 MMA, D += A*B (D==C in-place)
__device__ __forceinline__ void mma16816(float* d, const uint32_t* a, const uint32_t* b) {
    asm volatile(
        "mma.sync.aligned.m16n8k16.row.col.f32.bf16.bf16.f32 "
        "{%0,%1,%2,%3}, {%4,%5,%6,%7}, {%8,%9}, {%0,%1,%2,%3};"
        : "+f"(d[0]), "+f"(d[1]), "+f"(d[2]), "+f"(d[3])
        : "r"(a[0]), "r"(a[1]), "r"(a[2]), "r"(a[3]), "r"(b[0]), "r"(b[1]));
}

#define PSTR 20   // smem row stride in u32: conflict-free fragment access

// ---------------------------------------------------------------------------
// k_prep: zero deg + total, pack W1/W2 into bf16 hi/lo pairs. One kernel.
// ---------------------------------------------------------------------------
__global__ void k_prep(const float* __restrict__ W1, const float* __restrict__ W2, int N) {
    int i = blockIdx.x * blockDim.x + threadIdx.x;
    if (i < N) g_deg[i] = 0;
    if (i == 0) g_total = 0;
    if (i < 128 * 64) {
        int n = i >> 6, p = (i & 63) * 2;
        uint32_t h, l;
        split_pack(W1[(size_t)p * FHID + n], W1[(size_t)(p + 1) * FHID + n], h, l);
        g_W1h[i] = h; g_W1l[i] = l;
    } else if (i < 128 * 64 + 64 * 64) {
        int j = i - 128 * 64;
        int n = j >> 6, p = (j & 63) * 2;
        uint32_t h, l;
        split_pack(W2[(size_t)p * FOUT + n], W2[(size_t)(p + 1) * FOUT + n], h, l);
        g_W2h[j] = h; g_W2l[j] = l;
    }
}

__global__ void k_count(const int* __restrict__ col, int E) {
    int e = blockIdx.x * blockDim.x + threadIdx.x;
    if (e < E) atomicAdd(&g_deg[col[e]], 1);
}

// Single-pass scan: per-block scan + atomic global base; writes off/cursor/dinv.
// Block bases are assigned in nondeterministic order (sums unaffected); aggs use
// end = off[w] + deg[w], never off[w+1].
__global__ __launch_bounds__(1024) void k_scan1(int N) {
    __shared__ int s[1024];
    __shared__ int sbase;
    int t = threadIdx.x;
    int i = blockIdx.x * 1024 + t;
    int v = (i < N) ? g_deg[i] : 0;
    s[t] = v;
    __syncthreads();
#pragma unroll
    for (int d = 1; d < 1024; d <<= 1) {
        int x = s[t];
        if (t >= d) x += s[t - d];
        __syncthreads();
        s[t] = x;
        __syncthreads();
    }
    if (t == 1023) sbase = atomicAdd(&g_total, s[1023]);
    __syncthreads();
    if (i < N) {
        int o = sbase + s[t] - v;
        g_off[i]    = o;
        g_cursor[i] = o;
        g_dinv[i]   = rsqrtf((float)v + 1.0f);
    }
}

__global__ void k_place(const int* __restrict__ row, const int* __restrict__ col, int E) {
    int e = blockIdx.x * blockDim.x + threadIdx.x;
    if (e < E) {
        int c = col[e];
        int p = atomicAdd(&g_cursor[c], 1);
        g_eidx[p] = row[e];
    }
}

// ---------------------------------------------------------------------------
// GEMM1 (mma.sync bf16-split): Hsh = fp16(X @ W1)  -- UNSCALED (no dinv dep).
// CTA 128x128, 8 warps in 2m x 4n. K in 4 chunks of 32. B from packed weights.
// ---------------------------------------------------------------------------
__global__ __launch_bounds__(256) void k_gemm1(
    const float* __restrict__ X, int N)
{
    __shared__ uint32_t AsH[128 * PSTR], AsL[128 * PSTR];
    __shared__ uint32_t BsH[128 * PSTR], BsL[128 * PSTR];

    const int tid  = threadIdx.x;
    const int lane = tid & 31;
    const int wid  = tid >> 5;
    const int wm   = wid & 1;
    const int wn   = wid >> 1;
    const int bi   = blockIdx.x * 128;

    const int ar  = tid >> 1;
    const int akh = (tid & 1) * 16;
    const int arc = min(bi + ar, N - 1);
    const float* Xrow = X + (size_t)arc * FIN;

    const int bn  = tid >> 1;
    const int bp0 = (tid & 1) * 8;

    float acc[4][4][4];
#pragma unroll
    for (int mi = 0; mi < 4; mi++)
#pragma unroll
        for (int ni = 0; ni < 4; ni++)
#pragma unroll
            for (int q = 0; q < 4; q++) acc[mi][ni][q] = 0.f;

    for (int ch = 0; ch < 4; ch++) {
        const int kc = ch * 32;
        const int cp = ch * 16;
        __syncthreads();
#pragma unroll
        for (int i = 0; i < 4; i++) {
            float4 v = *(const float4*)&Xrow[kc + akh + 4 * i];
            uint32_t h0, l0, h1, l1;
            split_pack(v.x, v.y, h0, l0);
            split_pack(v.z, v.w, h1, l1);
            int p = ar * PSTR + (akh >> 1) + 2 * i;
            AsH[p] = h0; AsH[p + 1] = h1;
            AsL[p] = l0; AsL[p + 1] = l1;
        }
        {
            uint4 h0 = *(const uint4*)&g_W1h[bn * 64 + cp + bp0];
            uint4 h1 = *(const uint4*)&g_W1h[bn * 64 + cp + bp0 + 4];
            uint4 l0 = *(const uint4*)&g_W1l[bn * 64 + cp + bp0];
            uint4 l1 = *(const uint4*)&g_W1l[bn * 64 + cp + bp0 + 4];
            *(uint4*)&BsH[bn * PSTR + bp0]     = h0;
            *(uint4*)&BsH[bn * PSTR + bp0 + 4] = h1;
            *(uint4*)&BsL[bn * PSTR + bp0]     = l0;
            *(uint4*)&BsL[bn * PSTR + bp0 + 4] = l1;
        }
        __syncthreads();

#pragma unroll
        for (int ks = 0; ks < 2; ks++) {
            const int pb = ks * 8;
            uint32_t bh[4][2], bl[4][2], afr[4][4];
#pragma unroll
            for (int ni = 0; ni < 4; ni++) {
                int idx = (wn * 32 + ni * 8 + (lane >> 2)) * PSTR + pb + (lane & 3);
                bh[ni][0] = BsH[idx]; bh[ni][1] = BsH[idx + 4];
                bl[ni][0] = BsL[idx]; bl[ni][1] = BsL[idx + 4];
            }
#pragma unroll
            for (int mi = 0; mi < 4; mi++) {
                int rb = wm * 64 + mi * 16 + (lane >> 2);
                int i0 = rb * PSTR + pb + (lane & 3);
                int i1 = i0 + 8 * PSTR;
                afr[mi][0] = AsH[i0]; afr[mi][1] = AsH[i1];
                afr[mi][2] = AsH[i0 + 4]; afr[mi][3] = AsH[i1 + 4];
            }
#pragma unroll
            for (int mi = 0; mi < 4; mi++)
#pragma unroll
                for (int ni = 0; ni < 4; ni++) {
                    mma16816(acc[mi][ni], afr[mi], bh[ni]);   // hi*hi
                    mma16816(acc[mi][ni], afr[mi], bl[ni]);   // hi*lo
                }
#pragma unroll
            for (int mi = 0; mi < 4; mi++) {
                int rb = wm * 64 + mi * 16 + (lane >> 2);
                int i0 = rb * PSTR + pb + (lane & 3);
                int i1 = i0 + 8 * PSTR;
                afr[mi][0] = AsL[i0]; afr[mi][1] = AsL[i1];
                afr[mi][2] = AsL[i0 + 4]; afr[mi][3] = AsL[i1 + 4];
            }
#pragma unroll
            for (int mi = 0; mi < 4; mi++)
#pragma unroll
                for (int ni = 0; ni < 4; ni++)
                    mma16816(acc[mi][ni], afr[mi], bh[ni]);   // lo*hi
        }
    }

    // epilogue: UNSCALED fp16 store
#pragma unroll
    for (int mi = 0; mi < 4; mi++) {
        int r0 = bi + wm * 64 + mi * 16 + (lane >> 2);
        int r1 = r0 + 8;
#pragma unroll
        for (int ni = 0; ni < 4; ni++) {
            int c = wn * 32 + ni * 8 + (lane & 3) * 2;
            if (r0 < N) {
                __half2 v = __floats2half2_rn(acc[mi][ni][0], acc[mi][ni][1]);
                *(__half2*)&g_Hsh[(size_t)r0 * FHID + c] = v;
            }
            if (r1 < N) {
                __half2 v = __floats2half2_rn(acc[mi][ni][2], acc[mi][ni][3]);
                *(__half2*)&g_Hsh[(size_t)r1 * FHID + c] = v;
            }
        }
    }
}

// ---------------------------------------------------------------------------
// Agg1 (CSR gather, fp16, MLP=4): acc = dinv[w]*h[w] + sum dinv[r]*h[r];
// H2 = relu(dinv[w]*acc + b1). dinv shuffled alongside edge index.
// ---------------------------------------------------------------------------
__global__ __launch_bounds__(256) void k_agg1(const float* __restrict__ b1, int N) {
    int w    = (blockIdx.x * blockDim.x + threadIdx.x) >> 5;
    int lane = threadIdx.x & 31;
    if (w >= N) return;
    int beg = g_off[w];
    int end = beg + g_deg[w];
    float sw = g_dinv[w];

    const uint2 su = *(const uint2*)&g_Hsh[(size_t)w * FHID + lane * 4];
    float2 p0 = __half22float2(*(const __half2*)&su.x);
    float2 p1 = __half22float2(*(const __half2*)&su.y);
    float a0 = p0.x * sw, a1 = p0.y * sw, a2 = p1.x * sw, a3 = p1.y * sw;

    for (int j0 = beg; j0 < end; j0 += 32) {
        int jj = j0 + lane;
        int   myidx = (jj < end) ? g_eidx[jj] : 0;
        float mydv  = (jj < end) ? g_dinv[myidx] : 0.f;
        int m = min(32, end - j0);
        int t = 0;
        for (; t + 4 <= m; t += 4) {
            int   r0 = __shfl_sync(0xffffffffu, myidx, t);
            int   r1 = __shfl_sync(0xffffffffu, myidx, t + 1);
            int   r2 = __shfl_sync(0xffffffffu, myidx, t + 2);
            int   r3 = __shfl_sync(0xffffffffu, myidx, t + 3);
            float d0 = __shfl_sync(0xffffffffu, mydv, t);
            float d1 = __shfl_sync(0xffffffffu, mydv, t + 1);
            float d2 = __shfl_sync(0xffffffffu, mydv, t + 2);
            float d3 = __shfl_sync(0xffffffffu, mydv, t + 3);
            uint2 u0 = *(const uint2*)&g_Hsh[(size_t)r0 * FHID + lane * 4];
            uint2 u1 = *(const uint2*)&g_Hsh[(size_t)r1 * FHID + lane * 4];
            uint2 u2 = *(const uint2*)&g_Hsh[(size_t)r2 * FHID + lane * 4];
            uint2 u3 = *(const uint2*)&g_Hsh[(size_t)r3 * FHID + lane * 4];
            float2 q;
            q = __half22float2(*(const __half2*)&u0.x); a0 = fmaf(q.x, d0, a0); a1 = fmaf(q.y, d0, a1);
            q = __half22float2(*(const __half2*)&u0.y); a2 = fmaf(q.x, d0, a2); a3 = fmaf(q.y, d0, a3);
            q = __half22float2(*(const __half2*)&u1.x); a0 = fmaf(q.x, d1, a0); a1 = fmaf(q.y, d1, a1);
            q = __half22float2(*(const __half2*)&u1.y); a2 = fmaf(q.x, d1, a2); a3 = fmaf(q.y, d1, a3);
            q = __half22float2(*(const __half2*)&u2.x); a0 = fmaf(q.x, d2, a0); a1 = fmaf(q.y, d2, a1);
            q = __half22float2(*(const __half2*)&u2.y); a2 = fmaf(q.x, d2, a2); a3 = fmaf(q.y, d2, a3);
            q = __half22float2(*(const __half2*)&u3.x); a0 = fmaf(q.x, d3, a0); a1 = fmaf(q.y, d3, a1);
            q = __half22float2(*(const __half2*)&u3.y); a2 = fmaf(q.x, d3, a2); a3 = fmaf(q.y, d3, a3);
        }
        for (; t < m; t++) {
            int   r  = __shfl_sync(0xffffffffu, myidx, t);
            float dv = __shfl_sync(0xffffffffu, mydv, t);
            uint2 u = *(const uint2*)&g_Hsh[(size_t)r * FHID + lane * 4];
            float2 q;
            q = __half22float2(*(const __half2*)&u.x); a0 = fmaf(q.x, dv, a0); a1 = fmaf(q.y, dv, a1);
            q = __half22float2(*(const __half2*)&u.y); a2 = fmaf(q.x, dv, a2); a3 = fmaf(q.y, dv, a3);
        }
    }
    float4 bb = ((const float4*)b1)[lane];
    float4 o;
    o.x = fmaxf(fmaf(a0, sw, bb.x), 0.f);
    o.y = fmaxf(fmaf(a1, sw, bb.y), 0.f);
    o.z = fmaxf(fmaf(a2, sw, bb.z), 0.f);
    o.w = fmaxf(fmaf(a3, sw, bb.w), 0.f);
    ((float4*)g_H2)[(size_t)w * 32 + lane] = o;
}

// ---------------------------------------------------------------------------
// GEMM2 (mma.sync bf16-split): Hs2h = fp16((H2 @ W2) * dinv[row])
// CTA 128x64, 8 warps in 4m x 2n. K in 4 chunks of 32. B from packed weights.
// ---------------------------------------------------------------------------
__global__ __launch_bounds__(256) void k_gemm2(int N)
{
    __shared__ uint32_t AsH[128 * PSTR], AsL[128 * PSTR];
    __shared__ uint32_t BsH[64 * PSTR], BsL[64 * PSTR];

    const int tid  = threadIdx.x;
    const int lane = tid & 31;
    const int wid  = tid >> 5;
    const int wm   = wid & 3;
    const int wn   = wid >> 2;
    const int bi   = blockIdx.x * 128;

    const int ar  = tid >> 1;
    const int akh = (tid & 1) * 16;
    const int arc = min(bi + ar, N - 1);
    const float* Hrow = g_H2 + (size_t)arc * FHID;

    const int bn  = tid >> 2;
    const int bp0 = (tid & 3) * 4;

    float acc[2][4][4];
#pragma unroll
    for (int mi = 0; mi < 2; mi++)
#pragma unroll
        for (int ni = 0; ni < 4; ni++)
#pragma unroll
            for (int q = 0; q < 4; q++) acc[mi][ni][q] = 0.f;

    for (int ch = 0; ch < 4; ch++) {
        const int kc = ch * 32;
        const int cp = ch * 16;
        __syncthreads();
#pragma unroll
        for (int i = 0; i < 4; i++) {
            float4 v = *(const float4*)&Hrow[kc + akh + 4 * i];
            uint32_t h0, l0, h1, l1;
            split_pack(v.x, v.y, h0, l0);
            split_pack(v.z, v.w, h1, l1);
            int p = ar * PSTR + (akh >> 1) + 2 * i;
            AsH[p] = h0; AsH[p + 1] = h1;
            AsL[p] = l0; AsL[p + 1] = l1;
        }
        {
            uint4 h = *(const uint4*)&g_W2h[bn * 64 + cp + bp0];
            uint4 l = *(const uint4*)&g_W2l[bn * 64 + cp + bp0];
            *(uint4*)&BsH[bn * PSTR + bp0] = h;
            *(uint4*)&BsL[bn * PSTR + bp0] = l;
        }
        __syncthreads();

#pragma unroll
        for (int ks = 0; ks < 2; ks++) {
            const int pb = ks * 8;
            uint32_t bh[4][2], bl[4][2], afr[2][4];
#pragma unroll
            for (int ni = 0; ni < 4; ni++) {
                int idx = (wn * 32 + ni * 8 + (lane >> 2)) * PSTR + pb + (lane & 3);
                bh[ni][0] = BsH[idx]; bh[ni][1] = BsH[idx + 4];
                bl[ni][0] = BsL[idx]; bl[ni][1] = BsL[idx + 4];
            }
#pragma unroll
            for (int mi = 0; mi < 2; mi++) {
                int rb = wm * 32 + mi * 16 + (lane >> 2);
                int i0 = rb * PSTR + pb + (lane & 3);
                int i1 = i0 + 8 * PSTR;
                afr[mi][0] = AsH[i0]; afr[mi][1] = AsH[i1];
                afr[mi][2] = AsH[i0 + 4]; afr[mi][3] = AsH[i1 + 4];
            }
#pragma unroll
            for (int mi = 0; mi < 2; mi++)
#pragma unroll
                for (int ni = 0; ni < 4; ni++) {
                    mma16816(acc[mi][ni], afr[mi], bh[ni]);
                    mma16816(acc[mi][ni], afr[mi], bl[ni]);
                }
#pragma unroll
            for (int mi = 0; mi < 2; mi++) {
                int rb = wm * 32 + mi * 16 + (lane >> 2);
                int i0 = rb * PSTR + pb + (lane & 3);
                int i1 = i0 + 8 * PSTR;
                afr[mi][0] = AsL[i0]; afr[mi][1] = AsL[i1];
                afr[mi][2] = AsL[i0 + 4]; afr[mi][3] = AsL[i1 + 4];
            }
#pragma unroll
            for (int mi = 0; mi < 2; mi++)
#pragma unroll
                for (int ni = 0; ni < 4; ni++)
                    mma16816(acc[mi][ni], afr[mi], bh[ni]);
        }
    }

#pragma unroll
    for (int mi = 0; mi < 2; mi++) {
        int r0 = bi + wm * 32 + mi * 16 + (lane >> 2);
        int r1 = r0 + 8;
        float s0 = (r0 < N) ? g_dinv[r0] : 0.f;
        float s1 = (r1 < N) ? g_dinv[r1] : 0.f;
#pragma unroll
        for (int ni = 0; ni < 4; ni++) {
            int c = wn * 32 + ni * 8 + (lane & 3) * 2;
            if (r0 < N) {
                __half2 v = __floats2half2_rn(acc[mi][ni][0] * s0, acc[mi][ni][1] * s0);
                *(__half2*)&g_Hs2h[(size_t)r0 * FOUT + c] = v;
            }
            if (r1 < N) {
                __half2 v = __floats2half2_rn(acc[mi][ni][2] * s1, acc[mi][ni][3] * s1);
                *(__half2*)&g_Hs2h[(size_t)r1 * FOUT + c] = v;
            }
        }
    }
}

// ---------------------------------------------------------------------------
// Agg2 (CSR gather, fp16, MLP=4): one warp per node, lane = half2 (4 B).
// ---------------------------------------------------------------------------
__global__ __launch_bounds__(256) void k_agg2(
    const float* __restrict__ b2, float* __restrict__ out, int N)
{
    int w    = (blockIdx.x * blockDim.x + threadIdx.x) >> 5;
    int lane = threadIdx.x & 31;
    if (w >= N) return;
    int beg = g_off[w];
    int end = beg + g_deg[w];

    float2 acc = __half22float2(*(const __half2*)&g_Hs2h[(size_t)w * FOUT + lane * 2]);

    for (int j0 = beg; j0 < end; j0 += 32) {
        int jj = j0 + lane;
        int myidx = (jj < end) ? g_eidx[jj] : 0;
        int m = min(32, end - j0);
        int t = 0;
        for (; t + 4 <= m; t += 4) {
            int r0 = __shfl_sync(0xffffffffu, myidx, t);
            int r1 = __shfl_sync(0xffffffffu, myidx, t + 1);
            int r2 = __shfl_sync(0xffffffffu, myidx, t + 2);
            int r3 = __shfl_sync(0xffffffffu, myidx, t + 3);
            uint32_t u0 = *(const uint32_t*)&g_Hs2h[(size_t)r0 * FOUT + lane * 2];
            uint32_t u1 = *(const uint32_t*)&g_Hs2h[(size_t)r1 * FOUT + lane * 2];
            uint32_t u2 = *(const uint32_t*)&g_Hs2h[(size_t)r2 * FOUT + lane * 2];
            uint32_t u3 = *(const uint32_t*)&g_Hs2h[(size_t)r3 * FOUT + lane * 2];
            float2 q;
            q = __half22float2(*(const __half2*)&u0); acc.x += q.x; acc.y += q.y;
            q = __half22float2(*(const __half2*)&u1); acc.x += q.x; acc.y += q.y;
            q = __half22float2(*(const __half2*)&u2); acc.x += q.x; acc.y += q.y;
            q = __half22float2(*(const __half2*)&u3); acc.x += q.x; acc.y += q.y;
        }
        for (; t < m; t++) {
            int r = __shfl_sync(0xffffffffu, myidx, t);
            uint32_t u = *(const uint32_t*)&g_Hs2h[(size_t)r * FOUT + lane * 2];
            float2 q = __half22float2(*(const __half2*)&u);
            acc.x += q.x; acc.y += q.y;
        }
    }
    float s = g_dinv[w];
    float2 bb = ((const float2*)b2)[lane];
    float2 o;
    o.x = fmaf(acc.x, s, bb.x);
    o.y = fmaf(acc.y, s, bb.y);
    ((float2*)out)[(size_t)w * 32 + lane] = o;
}

// ---------------------------------------------------------------------------
// Launch: fork gemm1 onto a side stream, overlapping with CSR build.
// ---------------------------------------------------------------------------
extern "C" void kernel_launch(void* const* d_in, const int* in_sizes, int n_in,
                              void* d_out, int out_size)
{
    const float* x  = (const float*)d_in[0];
    const int*   ei = (const int*)  d_in[1];
    const float* W1 = (const float*)d_in[2];
    const float* b1 = (const float*)d_in[3];
    const float* W2 = (const float*)d_in[4];
    const float* b2 = (const float*)d_in[5];
    float* out = (float*)d_out;

    const int N = in_sizes[0] / FIN;     // 100000
    const int E = in_sizes[1] / 2;       // 1600000
    const int* row = ei;
    const int* col = ei + E;

    // Host-side stream/event objects (not device memory). Created per call;
    // intentionally not destroyed (kernel_launch runs only a handful of times)
    // to avoid any destroy-during-capture hazards.
    cudaStream_t s1;
    cudaEvent_t e0, e1;
    cudaStreamCreateWithFlags(&s1, cudaStreamNonBlocking);
    cudaEventCreateWithFlags(&e0, cudaEventDisableTiming);
    cudaEventCreateWithFlags(&e1, cudaEventDisableTiming);

    // Prep (weights + zeroing) on the origin stream.
    k_prep<<<(N + 255) / 256, 256>>>(W1, W2, N);

    // Fork: gemm1 depends only on prep (packed weights) + input X.
    cudaEventRecord(e0, 0);
    cudaStreamWaitEvent(s1, e0, 0);
    k_gemm1<<<(N + 127) / 128, 256, 0, s1>>>(x, N);
    cudaEventRecord(e1, s1);

    // CSR build on the origin stream, concurrent with gemm1.
    k_count<<<(E + 255) / 256, 256>>>(col, E);
    k_scan1<<<(N + 1023) / 1024, 1024>>>(N);
    k_place<<<(E + 255) / 256, 256>>>(row, col, E);

    // Join: agg1 needs both gemm1 and the CSR.
    cudaStreamWaitEvent(0, e1, 0);
    k_agg1<<<(N * 32 + 255) / 256, 256>>>(b1, N);

    // Layer 2 (serial).
    k_gemm2<<<(N + 127) / 128, 256>>>(N);
    k_agg2<<<(N * 32 + 255) / 256, 256>>>(b2, out, N);
}